// round 3
// baseline (speedup 1.0000x reference)
#include <cuda_runtime.h>
#include <mma.h>
#include <math.h>

using namespace nvcuda;

// ---------------------------------------------------------------------------
// HeteroGAT encoder.
//   - 6 GEMMs via 3xTF32 WMMA tensor cores (fp32-grade accuracy)
//   - direct store_matrix_sync epilogue (padded scratch outputs), bias via
//     accumulator preload from replicated smem tile
//   - dst-side attention scores via projected weights (no hd GEMM)
//   - CSR-by-dst; single-pass fused softmax+aggregate (smem-cached scores)
//   - fused LN + bias + relu + residual
// ---------------------------------------------------------------------------

#define NMAX 50176   // multiple of 128; >= padded grid coverage
#define EMAX 500000

__device__ float g_hA[NMAX * 128];
__device__ float g_hB[NMAX * 128];
__device__ float g_nA[NMAX * 128];
__device__ float g_nB[NMAX * 128];
__device__ float g_t1[NMAX * 128];
__device__ float g_t2[NMAX * 128];
__device__ float g_as1[NMAX * 4], g_ad1[NMAX * 4];
__device__ float g_as2[NMAX * 4], g_ad2[NMAX * 4];
__device__ float g_wpS1[128 * 4], g_wpD1[128 * 4];
__device__ float g_wpS2[128 * 4], g_wpD2[128 * 4];
__device__ int g_rpAB[NMAX + 1], g_rpBA[NMAX + 1];
__device__ int g_cur[NMAX], g_deg[NMAX];
__device__ int g_srcAB[EMAX], g_srcBA[EMAX];

__device__ __forceinline__ float warpSum(float v) {
#pragma unroll
    for (int o = 16; o > 0; o >>= 1) v += __shfl_xor_sync(0xffffffffu, v, o);
    return v;
}
__device__ __forceinline__ float warpMax(float v) {
#pragma unroll
    for (int o = 16; o > 0; o >>= 1) v = fmaxf(v, __shfl_xor_sync(0xffffffffu, v, o));
    return v;
}

// ---------------------------------------------------------------------------
// 3xTF32 WMMA GEMM: out[M,128] = X[M,K] @ W[K,128] (+ bias). K in {64,128}.
// 128x128 block tile, 256 threads = 8 warps, warp tile 32x64.
// out must be padded to >= gridDim.x*128 rows (all scratch is NMAX-padded).
// ---------------------------------------------------------------------------
#define XS_LD 36
#define WS_LD 132
#define BS_LD 132

__global__ __launch_bounds__(256) void gemm_tf32_128(
    const float* __restrict__ X, const float* __restrict__ W,
    const float* __restrict__ bias, float* __restrict__ out, int M, int K) {
    __shared__ float Xs[128][XS_LD];
    __shared__ float Ws[32][WS_LD];
    __shared__ float Bs[16][BS_LD];

    const int tid = threadIdx.x;
    const int wid = tid >> 5;
    const int block_row = blockIdx.x * 128;
    const int warp_row = (wid >> 1) * 32;   // 0,32,64,96
    const int warp_col = (wid & 1) * 64;    // 0,64

    // replicated bias tile (16 identical rows) for accumulator preload
    if (bias) {
#pragma unroll
        for (int i = tid; i < 16 * 128; i += 256) Bs[i >> 7][i & 127] = bias[i & 127];
        __syncthreads();
    }

    wmma::fragment<wmma::accumulator, 16, 16, 8, float> acc[2][4];
#pragma unroll
    for (int i = 0; i < 2; i++)
#pragma unroll
        for (int j = 0; j < 4; j++) {
            if (bias)
                wmma::load_matrix_sync(acc[i][j], &Bs[0][warp_col + j * 16], BS_LD,
                                       wmma::mem_row_major);
            else
                wmma::fill_fragment(acc[i][j], 0.f);
        }

    for (int k0 = 0; k0 < K; k0 += 32) {
        // X tile: 128 x 32 (float4 loads, zero-pad OOB rows)
#pragma unroll
        for (int p = 0; p < 4; p++) {
            int idx = tid + p * 256;           // 0..1023 float4 slots
            int r = idx >> 3;                  // 0..127
            int c4 = (idx & 7) * 4;            // 0..28
            int gr = block_row + r;
            float4 v = make_float4(0.f, 0.f, 0.f, 0.f);
            if (gr < M) v = *(const float4*)&X[(size_t)gr * K + k0 + c4];
            *(float4*)&Xs[r][c4] = v;
        }
        // W tile: 32 x 128
#pragma unroll
        for (int p = 0; p < 4; p++) {
            int idx = tid + p * 256;
            int r = idx >> 5;                  // 0..31
            int c4 = (idx & 31) * 4;           // 0..124
            *(float4*)&Ws[r][c4] = *(const float4*)&W[(size_t)(k0 + r) * 128 + c4];
        }
        __syncthreads();

#pragma unroll
        for (int ks = 0; ks < 32; ks += 8) {
            wmma::fragment<wmma::matrix_a, 16, 16, 8, wmma::precision::tf32, wmma::row_major> ahi[2], alo[2];
            wmma::fragment<wmma::matrix_b, 16, 16, 8, wmma::precision::tf32, wmma::row_major> bhi[4], blo[4];
#pragma unroll
            for (int i = 0; i < 2; i++) {
                wmma::load_matrix_sync(ahi[i], &Xs[warp_row + i * 16][ks], XS_LD);
#pragma unroll
                for (int t = 0; t < ahi[i].num_elements; t++) {
                    float x = ahi[i].x[t];
                    float hi = wmma::__float_to_tf32(x);
                    ahi[i].x[t] = hi;
                    alo[i].x[t] = wmma::__float_to_tf32(x - hi);
                }
            }
#pragma unroll
            for (int j = 0; j < 4; j++) {
                wmma::load_matrix_sync(bhi[j], &Ws[ks][warp_col + j * 16], WS_LD);
#pragma unroll
                for (int t = 0; t < bhi[j].num_elements; t++) {
                    float x = bhi[j].x[t];
                    float hi = wmma::__float_to_tf32(x);
                    bhi[j].x[t] = hi;
                    blo[j].x[t] = wmma::__float_to_tf32(x - hi);
                }
            }
#pragma unroll
            for (int i = 0; i < 2; i++)
#pragma unroll
                for (int j = 0; j < 4; j++) {
                    wmma::mma_sync(acc[i][j], ahi[i], blo[j], acc[i][j]);
                    wmma::mma_sync(acc[i][j], alo[i], bhi[j], acc[i][j]);
                    wmma::mma_sync(acc[i][j], ahi[i], bhi[j], acc[i][j]);
                }
        }
        __syncthreads();
    }

    // direct store: out is padded, full tile always writable (ldm=128, mult of 4)
#pragma unroll
    for (int i = 0; i < 2; i++)
#pragma unroll
        for (int j = 0; j < 4; j++) {
            size_t off = (size_t)(block_row + warp_row + i * 16) * 128 + warp_col + j * 16;
            wmma::store_matrix_sync(&out[off], acc[i][j], 128, wmma::mem_row_major);
        }
}

// ---------------------------------------------------------------------------
// wp[k,h] = sum_d W[k, h*D+d] * a[h*D+d]
// ---------------------------------------------------------------------------
template <int H>
__global__ void make_wp(const float* __restrict__ W, const float* __restrict__ avs,
                        const float* __restrict__ avd, float* __restrict__ wpS,
                        float* __restrict__ wpD) {
    const int D = 128 / H;
    int k = threadIdx.x;
#pragma unroll
    for (int h = 0; h < H; h++) {
        float ss = 0.f, sd = 0.f;
        for (int d = 0; d < D; d++) {
            float w = W[(size_t)k * 128 + h * D + d];
            ss += w * avs[h * D + d];
            sd += w * avd[h * D + d];
        }
        wpS[k * H + h] = ss;
        wpD[k * H + h] = sd;
    }
}

// ---------------------------------------------------------------------------
// fused node scores: read X once, compute src-scores (wpS) and dst-scores (wpD)
// ---------------------------------------------------------------------------
template <int H>
__global__ void node_scores2(const float* __restrict__ X, const float* __restrict__ wpS,
                             const float* __restrict__ wpD, float* __restrict__ outS,
                             float* __restrict__ outD, int N) {
    int w = (blockIdx.x * blockDim.x + threadIdx.x) >> 5;
    int lane = threadIdx.x & 31;
    if (w >= N) return;
    const float* xr = X + (size_t)w * 128;
    float accS[H], accD[H];
#pragma unroll
    for (int h = 0; h < H; h++) { accS[h] = 0.f; accD[h] = 0.f; }
#pragma unroll
    for (int kk = 0; kk < 4; kk++) {
        int k = lane + kk * 32;
        float x = xr[k];
#pragma unroll
        for (int h = 0; h < H; h++) {
            accS[h] += x * wpS[k * H + h];
            accD[h] += x * wpD[k * H + h];
        }
    }
#pragma unroll
    for (int h = 0; h < H; h++) { accS[h] = warpSum(accS[h]); accD[h] = warpSum(accD[h]); }
    if (lane == 0) {
#pragma unroll
        for (int h = 0; h < H; h++) { outS[w * H + h] = accS[h]; outD[w * H + h] = accD[h]; }
    }
}

// ---------------------------------------------------------------------------
// CSR build
// ---------------------------------------------------------------------------
__global__ void edge_hist(const int* __restrict__ dst, int* __restrict__ deg, int E) {
    int e = blockIdx.x * blockDim.x + threadIdx.x;
    if (e < E) atomicAdd(&deg[dst[e]], 1);
}
__global__ void edge_fill(const int* __restrict__ src, const int* __restrict__ dst,
                          int* __restrict__ cursor, int* __restrict__ col, int E) {
    int e = blockIdx.x * blockDim.x + threadIdx.x;
    if (e < E) {
        int p = atomicAdd(&cursor[dst[e]], 1);
        col[p] = src[e];
    }
}
__global__ void exscan_block(const int* __restrict__ deg, int* __restrict__ rowptr,
                             int* __restrict__ cursor, int N) {
    __shared__ int sums[256];
    int t = threadIdx.x;
    int chunk = (N + 255) / 256;
    int b0 = t * chunk;
    int b1 = min(b0 + chunk, N);
    int s = 0;
    for (int i = b0; i < b1; i++) s += deg[i];
    sums[t] = s;
    __syncthreads();
    for (int off = 1; off < 256; off <<= 1) {
        int v = (t >= off) ? sums[t - off] : 0;
        __syncthreads();
        sums[t] += v;
        __syncthreads();
    }
    int run = (t == 0) ? 0 : sums[t - 1];
    for (int i = b0; i < b1; i++) {
        rowptr[i] = run;
        cursor[i] = run;
        run += deg[i];
    }
    if (t == 255) rowptr[N] = run;
}

// ---------------------------------------------------------------------------
// fused GAT aggregation, single-pass with smem-cached scores (deg<=128).
// warp per destination node, 8 warps / block.
// ---------------------------------------------------------------------------
template <int H>
__global__ __launch_bounds__(256) void gat_aggregate(
    const int* __restrict__ rowptr, const int* __restrict__ srcs,
    const float* __restrict__ a_s, const float* __restrict__ a_d,
    const float* __restrict__ tS, float* __restrict__ outp, int Ndst) {
    const int D = 128 / H;
    const int CAP = 128;
    __shared__ float s_ex[8][CAP * H];
    __shared__ int s_src[8][CAP];

    int wid = (blockIdx.x * blockDim.x + threadIdx.x) >> 5;
    int w = threadIdx.x >> 5;
    int lane = threadIdx.x & 31;
    if (wid >= Ndst) return;
    int start = rowptr[wid];
    int end = rowptr[wid + 1];
    int deg = end - start;

    float adh[H];
#pragma unroll
    for (int h = 0; h < H; h++) adh[h] = a_d[wid * H + h];

    const int hh = (lane * 4) / D;  // head for this lane's 4 channels
    float4 acc = make_float4(0.f, 0.f, 0.f, 0.f);

    if (deg <= CAP) {
        float sc[4][H];
        int nIt = (deg + 31) >> 5;
        float mx[H];
#pragma unroll
        for (int h = 0; h < H; h++) mx[h] = -3.0e38f;
#pragma unroll
        for (int i = 0; i < 4; i++) {
            int j = lane + i * 32;
            if (i < nIt && j < deg) {
                int s = srcs[start + j];
                s_src[w][j] = s;
#pragma unroll
                for (int h = 0; h < H; h++) {
                    float v = a_s[s * H + h] + adh[h];
                    v = v > 0.f ? v : 0.2f * v;
                    sc[i][h] = v;
                    mx[h] = fmaxf(mx[h], v);
                }
            }
        }
#pragma unroll
        for (int h = 0; h < H; h++) mx[h] = warpMax(mx[h]);

        float sm[H];
#pragma unroll
        for (int h = 0; h < H; h++) sm[h] = 0.f;
#pragma unroll
        for (int i = 0; i < 4; i++) {
            int j = lane + i * 32;
            if (i < nIt && j < deg) {
#pragma unroll
                for (int h = 0; h < H; h++) {
                    float ex = __expf(sc[i][h] - mx[h]);
                    sm[h] += ex;
                    s_ex[w][j * H + h] = ex;
                }
            }
        }
#pragma unroll
        for (int h = 0; h < H; h++) sm[h] = warpSum(sm[h]);

        float invh;
        if (H == 1) invh = 1.f / (sm[0] + 1e-16f);
        else invh = 1.f / ((hh == 0 ? sm[0] : hh == 1 ? sm[1] : hh == 2 ? sm[2] : sm[3]) + 1e-16f);

        __syncwarp();
        for (int e = 0; e < deg; e++) {
            float ex = s_ex[w][e * H + hh];
            int s = s_src[w][e];
            float4 v = *(const float4*)(tS + (size_t)s * 128 + lane * 4);
            acc.x += v.x * ex;
            acc.y += v.y * ex;
            acc.z += v.z * ex;
            acc.w += v.w * ex;
        }
        acc.x *= invh; acc.y *= invh; acc.z *= invh; acc.w *= invh;
    } else {
        float mx[H];
#pragma unroll
        for (int h = 0; h < H; h++) mx[h] = -3.0e38f;
        for (int e = start + lane; e < end; e += 32) {
            int s = srcs[e];
#pragma unroll
            for (int h = 0; h < H; h++) {
                float v = a_s[s * H + h] + adh[h];
                v = v > 0.f ? v : 0.2f * v;
                mx[h] = fmaxf(mx[h], v);
            }
        }
#pragma unroll
        for (int h = 0; h < H; h++) mx[h] = warpMax(mx[h]);
        float sm[H];
#pragma unroll
        for (int h = 0; h < H; h++) sm[h] = 0.f;
        for (int e = start + lane; e < end; e += 32) {
            int s = srcs[e];
#pragma unroll
            for (int h = 0; h < H; h++) {
                float v = a_s[s * H + h] + adh[h];
                v = v > 0.f ? v : 0.2f * v;
                sm[h] += __expf(v - mx[h]);
            }
        }
#pragma unroll
        for (int h = 0; h < H; h++) sm[h] = warpSum(sm[h]);
        float invh;
        if (H == 1) invh = 1.f / (sm[0] + 1e-16f);
        else invh = 1.f / ((hh == 0 ? sm[0] : hh == 1 ? sm[1] : hh == 2 ? sm[2] : sm[3]) + 1e-16f);
        float mxh = (H == 1) ? mx[0] : (hh == 0 ? mx[0] : hh == 1 ? mx[1] : hh == 2 ? mx[2] : mx[3]);
        float adhh = (H == 1) ? adh[0] : (hh == 0 ? adh[0] : hh == 1 ? adh[1] : hh == 2 ? adh[2] : adh[3]);
        for (int e = start; e < end; e++) {
            int s = srcs[e];
            float v = a_s[s * H + hh] + adhh;
            v = v > 0.f ? v : 0.2f * v;
            float ex = __expf(v - mxh);
            float4 t = *(const float4*)(tS + (size_t)s * 128 + lane * 4);
            acc.x += t.x * ex;
            acc.y += t.y * ex;
            acc.z += t.z * ex;
            acc.w += t.w * ex;
        }
        acc.x *= invh; acc.y *= invh; acc.z *= invh; acc.w *= invh;
    }
    *(float4*)(outp + (size_t)wid * 128 + lane * 4) = acc;
}

// ---------------------------------------------------------------------------
// fused: h_out = relu(LN(n + bias) * g + b) + h_prev   (warp per node)
// ---------------------------------------------------------------------------
__global__ void ln_relu_residual(const float* __restrict__ nbuf, const float* __restrict__ bias,
                                 const float* __restrict__ gamma, const float* __restrict__ beta,
                                 const float* __restrict__ hprev, float* __restrict__ hout,
                                 int N) {
    int wid = (blockIdx.x * blockDim.x + threadIdx.x) >> 5;
    int lane = threadIdx.x & 31;
    if (wid >= N) return;
    size_t base = (size_t)wid * 128 + lane * 4;
    float4 v = *(const float4*)(nbuf + base);
    float4 bb = *(const float4*)(bias + lane * 4);
    v.x += bb.x; v.y += bb.y; v.z += bb.z; v.w += bb.w;
    float mu = warpSum(v.x + v.y + v.z + v.w) * (1.f / 128.f);
    float dx = v.x - mu, dy = v.y - mu, dz = v.z - mu, dw = v.w - mu;
    float var = warpSum(dx * dx + dy * dy + dz * dz + dw * dw) * (1.f / 128.f);
    float r = rsqrtf(var + 1e-5f);
    float4 g = *(const float4*)(gamma + lane * 4);
    float4 b = *(const float4*)(beta + lane * 4);
    float4 hp = *(const float4*)(hprev + base);
    float4 o;
    o.x = fmaxf(0.f, dx * r * g.x + b.x) + hp.x;
    o.y = fmaxf(0.f, dy * r * g.y + b.y) + hp.y;
    o.z = fmaxf(0.f, dz * r * g.z + b.z) + hp.z;
    o.w = fmaxf(0.f, dw * r * g.w + b.w) + hp.w;
    *(float4*)(hout + base) = o;
}

// ---------------------------------------------------------------------------
static inline void* sym(const void* s) {
    void* p = nullptr;
    cudaGetSymbolAddress(&p, s);
    return p;
}

extern "C" void kernel_launch(void* const* d_in, const int* in_sizes, int n_in,
                              void* d_out, int out_size) {
    const float* x_A = (const float*)d_in[0];
    const float* x_B = (const float*)d_in[1];
    const float* pWA = (const float*)d_in[2];
    const float* pbA = (const float*)d_in[3];
    const float* pWB = (const float*)d_in[4];
    const float* pbB = (const float*)d_in[5];
    const float* w0ab = (const float*)d_in[6];
    const float* as0ab = (const float*)d_in[7];
    const float* ad0ab = (const float*)d_in[8];
    const float* b0ab = (const float*)d_in[9];
    const float* w0ba = (const float*)d_in[10];
    const float* as0ba = (const float*)d_in[11];
    const float* ad0ba = (const float*)d_in[12];
    const float* b0ba = (const float*)d_in[13];
    const float* w1ab = (const float*)d_in[14];
    const float* as1ab = (const float*)d_in[15];
    const float* ad1ab = (const float*)d_in[16];
    const float* b1ab = (const float*)d_in[17];
    const float* w1ba = (const float*)d_in[18];
    const float* as1ba = (const float*)d_in[19];
    const float* ad1ba = (const float*)d_in[20];
    const float* b1ba = (const float*)d_in[21];
    const float* g0A = (const float*)d_in[22];
    const float* bn0A = (const float*)d_in[23];
    const float* g0B = (const float*)d_in[24];
    const float* bn0B = (const float*)d_in[25];
    const float* g1A = (const float*)d_in[26];
    const float* bn1A = (const float*)d_in[27];
    const float* g1B = (const float*)d_in[28];
    const float* bn1B = (const float*)d_in[29];
    const int* ei_AB = (const int*)d_in[30];
    const int* ei_BA = (const int*)d_in[31];

    const int NA = in_sizes[0] / 128;
    const int NB = in_sizes[1] / 64;
    const int E = in_sizes[30] / 2;

    float* hA = (float*)sym(g_hA);
    float* hB = (float*)sym(g_hB);
    float* nA = (float*)sym(g_nA);
    float* nB = (float*)sym(g_nB);
    float* t1 = (float*)sym(g_t1);
    float* t2 = (float*)sym(g_t2);
    float* as1 = (float*)sym(g_as1);
    float* ad1 = (float*)sym(g_ad1);
    float* as2 = (float*)sym(g_as2);
    float* ad2 = (float*)sym(g_ad2);
    float* wpS1 = (float*)sym(g_wpS1);
    float* wpD1 = (float*)sym(g_wpD1);
    float* wpS2 = (float*)sym(g_wpS2);
    float* wpD2 = (float*)sym(g_wpD2);
    int* rpAB = (int*)sym(g_rpAB);
    int* rpBA = (int*)sym(g_rpBA);
    int* cur = (int*)sym(g_cur);
    int* deg = (int*)sym(g_deg);
    int* srcAB = (int*)sym(g_srcAB);
    int* srcBA = (int*)sym(g_srcBA);

    const int TB = 256;
    const int eb = (E + TB - 1) / TB;
    const int wbA = (NA * 32 + TB - 1) / TB;
    const int wbB = (NB * 32 + TB - 1) / TB;
    const int gbA = (NA + 127) / 128;
    const int gbB = (NB + 127) / 128;

    // --- CSR by destination, both directions (edges layer-invariant) ---
    cudaMemsetAsync(deg, 0, NB * sizeof(int));
    edge_hist<<<eb, TB>>>(ei_AB + E, deg, E);
    exscan_block<<<1, 256>>>(deg, rpAB, cur, NB);
    edge_fill<<<eb, TB>>>(ei_AB, ei_AB + E, cur, srcAB, E);

    cudaMemsetAsync(deg, 0, NA * sizeof(int));
    edge_hist<<<eb, TB>>>(ei_BA + E, deg, E);
    exscan_block<<<1, 256>>>(deg, rpBA, cur, NA);
    edge_fill<<<eb, TB>>>(ei_BA, ei_BA + E, cur, srcBA, E);

    // --- input projections ---
    gemm_tf32_128<<<gbA, TB>>>(x_A, pWA, pbA, hA, NA, 128);
    gemm_tf32_128<<<gbB, TB>>>(x_B, pWB, pbB, hB, NB, 64);

    // ================= layer 0 (H=4, D=32) =================
    make_wp<4><<<1, 128>>>(w0ab, as0ab, ad0ab, wpS1, wpD1);
    make_wp<4><<<1, 128>>>(w0ba, as0ba, ad0ba, wpS2, wpD2);

    gemm_tf32_128<<<gbA, TB>>>(hA, w0ab, nullptr, t1, NA, 128);
    gemm_tf32_128<<<gbB, TB>>>(hB, w0ba, nullptr, t2, NB, 128);

    node_scores2<4><<<wbA, TB>>>(hA, wpS1, wpD2, as1, ad2, NA);  // A: src(AB), dst(BA)
    node_scores2<4><<<wbB, TB>>>(hB, wpS2, wpD1, as2, ad1, NB);  // B: src(BA), dst(AB)

    gat_aggregate<4><<<wbB, TB>>>(rpAB, srcAB, as1, ad1, t1, nB, NB);
    gat_aggregate<4><<<wbA, TB>>>(rpBA, srcBA, as2, ad2, t2, nA, NA);

    ln_relu_residual<<<wbA, TB>>>(nA, b0ba, g0A, bn0A, hA, hA, NA);
    ln_relu_residual<<<wbB, TB>>>(nB, b0ab, g0B, bn0B, hB, hB, NB);

    // ================= layer 1 (H=1, D=128) =================
    make_wp<1><<<1, 128>>>(w1ab, as1ab, ad1ab, wpS1, wpD1);
    make_wp<1><<<1, 128>>>(w1ba, as1ba, ad1ba, wpS2, wpD2);

    gemm_tf32_128<<<gbA, TB>>>(hA, w1ab, nullptr, t1, NA, 128);
    gemm_tf32_128<<<gbB, TB>>>(hB, w1ba, nullptr, t2, NB, 128);

    node_scores2<1><<<wbA, TB>>>(hA, wpS1, wpD2, as1, ad2, NA);
    node_scores2<1><<<wbB, TB>>>(hB, wpS2, wpD1, as2, ad1, NB);

    gat_aggregate<1><<<wbB, TB>>>(rpAB, srcAB, as1, ad1, t1, nB, NB);
    gat_aggregate<1><<<wbA, TB>>>(rpBA, srcBA, as2, ad2, t2, nA, NA);

    float* outA = (float*)d_out;
    float* outB = outA + (size_t)NA * 128;
    ln_relu_residual<<<wbA, TB>>>(nA, b1ba, g1A, bn1A, hA, outA, NA);
    ln_relu_residual<<<wbB, TB>>>(nB, b1ab, g1B, bn1B, hB, outB, NB);
}

// round 4
// speedup vs baseline: 1.2547x; 1.2547x over previous
#include <cuda_runtime.h>
#include <cuda_bf16.h>
#include <mma.h>
#include <math.h>

using namespace nvcuda;

// ---------------------------------------------------------------------------
// HeteroGAT encoder.
//   - 6 GEMMs via bf16 split-3 WMMA (hi/lo split done once at smem fill;
//     hot loop = pure bf16 m16n16k16 MMAs, fp32 accumulate)
//   - dst-side attention scores via projected weights (no hd GEMM)
//   - CSR-by-dst; single-pass fused softmax+aggregate (smem-cached scores)
//   - fused LN + bias + relu + residual
// ---------------------------------------------------------------------------

#define NMAX 50176   // multiple of 128; >= padded grid coverage
#define EMAX 500000

__device__ float g_hA[NMAX * 128];
__device__ float g_hB[NMAX * 128];
__device__ float g_nA[NMAX * 128];
__device__ float g_nB[NMAX * 128];
__device__ float g_t1[NMAX * 128];
__device__ float g_t2[NMAX * 128];
__device__ float g_as1[NMAX * 4], g_ad1[NMAX * 4];
__device__ float g_as2[NMAX * 4], g_ad2[NMAX * 4];
__device__ float g_wpS1[128 * 4], g_wpD1[128 * 4];
__device__ float g_wpS2[128 * 4], g_wpD2[128 * 4];
__device__ int g_rpAB[NMAX + 1], g_rpBA[NMAX + 1];
__device__ int g_cur[NMAX], g_deg[NMAX];
__device__ int g_srcAB[EMAX], g_srcBA[EMAX];

__device__ __forceinline__ float warpSum(float v) {
#pragma unroll
    for (int o = 16; o > 0; o >>= 1) v += __shfl_xor_sync(0xffffffffu, v, o);
    return v;
}
__device__ __forceinline__ float warpMax(float v) {
#pragma unroll
    for (int o = 16; o > 0; o >>= 1) v = fmaxf(v, __shfl_xor_sync(0xffffffffu, v, o));
    return v;
}

// ---------------------------------------------------------------------------
// bf16 split-3 WMMA GEMM: out[M,128] = X[M,K] @ W[K,128] (+ bias).
// 128x128 block tile, 256 threads = 8 warps, warp tile 32x64.
// x = hi + lo (bf16 each); x*w ~= xh*wh + xh*wl + xl*wh (xl*wl ~2^-18, dropped)
// out must be padded to >= gridDim.x*128 rows (all scratch is NMAX-padded).
// ---------------------------------------------------------------------------
#define XA_LD 40    // bf16 elems per row: rows 80B (16B aligned), conflict-free
#define WB_LD 136   // bf16 elems per row: rows 272B (16B aligned), conflict-free
#define BS_LD 136

__global__ __launch_bounds__(256) void gemm_bf16s3_128(
    const float* __restrict__ X, const float* __restrict__ W,
    const float* __restrict__ bias, float* __restrict__ out, int M, int K) {
    __shared__ __nv_bfloat16 Xhi[128][XA_LD];
    __shared__ __nv_bfloat16 Xlo[128][XA_LD];
    __shared__ __nv_bfloat16 Whi[32][WB_LD];
    __shared__ __nv_bfloat16 Wlo[32][WB_LD];
    __shared__ float Bs[16][BS_LD];

    const int tid = threadIdx.x;
    const int wid = tid >> 5;
    const int block_row = blockIdx.x * 128;
    const int warp_row = (wid >> 1) * 32;   // 0,32,64,96
    const int warp_col = (wid & 1) * 64;    // 0,64

    if (bias) {
#pragma unroll
        for (int i = tid; i < 16 * 128; i += 256) Bs[i >> 7][i & 127] = bias[i & 127];
        __syncthreads();
    }

    wmma::fragment<wmma::accumulator, 16, 16, 16, float> acc[2][4];
#pragma unroll
    for (int i = 0; i < 2; i++)
#pragma unroll
        for (int j = 0; j < 4; j++) {
            if (bias)
                wmma::load_matrix_sync(acc[i][j], &Bs[0][warp_col + j * 16], BS_LD,
                                       wmma::mem_row_major);
            else
                wmma::fill_fragment(acc[i][j], 0.f);
        }

    for (int k0 = 0; k0 < K; k0 += 32) {
        // X tile: 128 x 32, split to bf16 hi/lo
#pragma unroll
        for (int p = 0; p < 4; p++) {
            int idx = tid + p * 256;           // 0..1023 float4 slots
            int r = idx >> 3;                  // 0..127
            int c4 = (idx & 7) * 4;            // 0..28
            int gr = block_row + r;
            float4 v = make_float4(0.f, 0.f, 0.f, 0.f);
            if (gr < M) v = *(const float4*)&X[(size_t)gr * K + k0 + c4];
            float vv[4] = {v.x, v.y, v.z, v.w};
#pragma unroll
            for (int q = 0; q < 4; q++) {
                __nv_bfloat16 hi = __float2bfloat16(vv[q]);
                __nv_bfloat16 lo = __float2bfloat16(vv[q] - __bfloat162float(hi));
                Xhi[r][c4 + q] = hi;
                Xlo[r][c4 + q] = lo;
            }
        }
        // W tile: 32 x 128, split to bf16 hi/lo
#pragma unroll
        for (int p = 0; p < 4; p++) {
            int idx = tid + p * 256;
            int r = idx >> 5;                  // 0..31
            int c4 = (idx & 31) * 4;           // 0..124
            float4 v = *(const float4*)&W[(size_t)(k0 + r) * 128 + c4];
            float vv[4] = {v.x, v.y, v.z, v.w};
#pragma unroll
            for (int q = 0; q < 4; q++) {
                __nv_bfloat16 hi = __float2bfloat16(vv[q]);
                __nv_bfloat16 lo = __float2bfloat16(vv[q] - __bfloat162float(hi));
                Whi[r][c4 + q] = hi;
                Wlo[r][c4 + q] = lo;
            }
        }
        __syncthreads();

#pragma unroll
        for (int ks = 0; ks < 32; ks += 16) {
            wmma::fragment<wmma::matrix_a, 16, 16, 16, __nv_bfloat16, wmma::row_major> ahi[2], alo[2];
            wmma::fragment<wmma::matrix_b, 16, 16, 16, __nv_bfloat16, wmma::row_major> bhi[4], blo[4];
#pragma unroll
            for (int i = 0; i < 2; i++) {
                wmma::load_matrix_sync(ahi[i], &Xhi[warp_row + i * 16][ks], XA_LD);
                wmma::load_matrix_sync(alo[i], &Xlo[warp_row + i * 16][ks], XA_LD);
            }
#pragma unroll
            for (int j = 0; j < 4; j++) {
                wmma::load_matrix_sync(bhi[j], &Whi[ks][warp_col + j * 16], WB_LD);
                wmma::load_matrix_sync(blo[j], &Wlo[ks][warp_col + j * 16], WB_LD);
            }
#pragma unroll
            for (int i = 0; i < 2; i++)
#pragma unroll
                for (int j = 0; j < 4; j++) {
                    wmma::mma_sync(acc[i][j], ahi[i], blo[j], acc[i][j]);
                    wmma::mma_sync(acc[i][j], alo[i], bhi[j], acc[i][j]);
                    wmma::mma_sync(acc[i][j], ahi[i], bhi[j], acc[i][j]);
                }
        }
        __syncthreads();
    }

    // direct store: out is padded, full tile always writable (ldm=128)
#pragma unroll
    for (int i = 0; i < 2; i++)
#pragma unroll
        for (int j = 0; j < 4; j++) {
            size_t off = (size_t)(block_row + warp_row + i * 16) * 128 + warp_col + j * 16;
            wmma::store_matrix_sync(&out[off], acc[i][j], 128, wmma::mem_row_major);
        }
}

// ---------------------------------------------------------------------------
// wp[k,h] = sum_d W[k, h*D+d] * a[h*D+d]
// ---------------------------------------------------------------------------
template <int H>
__global__ void make_wp(const float* __restrict__ W, const float* __restrict__ avs,
                        const float* __restrict__ avd, float* __restrict__ wpS,
                        float* __restrict__ wpD) {
    const int D = 128 / H;
    int k = threadIdx.x;
#pragma unroll
    for (int h = 0; h < H; h++) {
        float ss = 0.f, sd = 0.f;
        for (int d = 0; d < D; d++) {
            float w = W[(size_t)k * 128 + h * D + d];
            ss += w * avs[h * D + d];
            sd += w * avd[h * D + d];
        }
        wpS[k * H + h] = ss;
        wpD[k * H + h] = sd;
    }
}

// ---------------------------------------------------------------------------
// fused node scores: read X once, compute src-scores (wpS) and dst-scores (wpD)
// ---------------------------------------------------------------------------
template <int H>
__global__ void node_scores2(const float* __restrict__ X, const float* __restrict__ wpS,
                             const float* __restrict__ wpD, float* __restrict__ outS,
                             float* __restrict__ outD, int N) {
    int w = (blockIdx.x * blockDim.x + threadIdx.x) >> 5;
    int lane = threadIdx.x & 31;
    if (w >= N) return;
    const float* xr = X + (size_t)w * 128;
    float accS[H], accD[H];
#pragma unroll
    for (int h = 0; h < H; h++) { accS[h] = 0.f; accD[h] = 0.f; }
#pragma unroll
    for (int kk = 0; kk < 4; kk++) {
        int k = lane + kk * 32;
        float x = xr[k];
#pragma unroll
        for (int h = 0; h < H; h++) {
            accS[h] += x * wpS[k * H + h];
            accD[h] += x * wpD[k * H + h];
        }
    }
#pragma unroll
    for (int h = 0; h < H; h++) { accS[h] = warpSum(accS[h]); accD[h] = warpSum(accD[h]); }
    if (lane == 0) {
#pragma unroll
        for (int h = 0; h < H; h++) { outS[w * H + h] = accS[h]; outD[w * H + h] = accD[h]; }
    }
}

// ---------------------------------------------------------------------------
// CSR build
// ---------------------------------------------------------------------------
__global__ void edge_hist(const int* __restrict__ dst, int* __restrict__ deg, int E) {
    int e = blockIdx.x * blockDim.x + threadIdx.x;
    if (e < E) atomicAdd(&deg[dst[e]], 1);
}
__global__ void edge_fill(const int* __restrict__ src, const int* __restrict__ dst,
                          int* __restrict__ cursor, int* __restrict__ col, int E) {
    int e = blockIdx.x * blockDim.x + threadIdx.x;
    if (e < E) {
        int p = atomicAdd(&cursor[dst[e]], 1);
        col[p] = src[e];
    }
}
__global__ void exscan_block(const int* __restrict__ deg, int* __restrict__ rowptr,
                             int* __restrict__ cursor, int N) {
    __shared__ int sums[256];
    int t = threadIdx.x;
    int chunk = (N + 255) / 256;
    int b0 = t * chunk;
    int b1 = min(b0 + chunk, N);
    int s = 0;
    for (int i = b0; i < b1; i++) s += deg[i];
    sums[t] = s;
    __syncthreads();
    for (int off = 1; off < 256; off <<= 1) {
        int v = (t >= off) ? sums[t - off] : 0;
        __syncthreads();
        sums[t] += v;
        __syncthreads();
    }
    int run = (t == 0) ? 0 : sums[t - 1];
    for (int i = b0; i < b1; i++) {
        rowptr[i] = run;
        cursor[i] = run;
        run += deg[i];
    }
    if (t == 255) rowptr[N] = run;
}

// ---------------------------------------------------------------------------
// fused GAT aggregation, single-pass with smem-cached scores (deg<=128).
// warp per destination node, 8 warps / block.
// ---------------------------------------------------------------------------
template <int H>
__global__ __launch_bounds__(256) void gat_aggregate(
    const int* __restrict__ rowptr, const int* __restrict__ srcs,
    const float* __restrict__ a_s, const float* __restrict__ a_d,
    const float* __restrict__ tS, float* __restrict__ outp, int Ndst) {
    const int D = 128 / H;
    const int CAP = 128;
    __shared__ float s_ex[8][CAP * H];
    __shared__ int s_src[8][CAP];

    int wid = (blockIdx.x * blockDim.x + threadIdx.x) >> 5;
    int w = threadIdx.x >> 5;
    int lane = threadIdx.x & 31;
    if (wid >= Ndst) return;
    int start = rowptr[wid];
    int end = rowptr[wid + 1];
    int deg = end - start;

    float adh[H];
#pragma unroll
    for (int h = 0; h < H; h++) adh[h] = a_d[wid * H + h];

    const int hh = (lane * 4) / D;  // head for this lane's 4 channels
    float4 acc = make_float4(0.f, 0.f, 0.f, 0.f);

    if (deg <= CAP) {
        float sc[4][H];
        int nIt = (deg + 31) >> 5;
        float mx[H];
#pragma unroll
        for (int h = 0; h < H; h++) mx[h] = -3.0e38f;
#pragma unroll
        for (int i = 0; i < 4; i++) {
            int j = lane + i * 32;
            if (i < nIt && j < deg) {
                int s = srcs[start + j];
                s_src[w][j] = s;
#pragma unroll
                for (int h = 0; h < H; h++) {
                    float v = a_s[s * H + h] + adh[h];
                    v = v > 0.f ? v : 0.2f * v;
                    sc[i][h] = v;
                    mx[h] = fmaxf(mx[h], v);
                }
            }
        }
#pragma unroll
        for (int h = 0; h < H; h++) mx[h] = warpMax(mx[h]);

        float sm[H];
#pragma unroll
        for (int h = 0; h < H; h++) sm[h] = 0.f;
#pragma unroll
        for (int i = 0; i < 4; i++) {
            int j = lane + i * 32;
            if (i < nIt && j < deg) {
#pragma unroll
                for (int h = 0; h < H; h++) {
                    float ex = __expf(sc[i][h] - mx[h]);
                    sm[h] += ex;
                    s_ex[w][j * H + h] = ex;
                }
            }
        }
#pragma unroll
        for (int h = 0; h < H; h++) sm[h] = warpSum(sm[h]);

        float invh;
        if (H == 1) invh = 1.f / (sm[0] + 1e-16f);
        else invh = 1.f / ((hh == 0 ? sm[0] : hh == 1 ? sm[1] : hh == 2 ? sm[2] : sm[3]) + 1e-16f);

        __syncwarp();
        for (int e = 0; e < deg; e++) {
            float ex = s_ex[w][e * H + hh];
            int s = s_src[w][e];
            float4 v = *(const float4*)(tS + (size_t)s * 128 + lane * 4);
            acc.x += v.x * ex;
            acc.y += v.y * ex;
            acc.z += v.z * ex;
            acc.w += v.w * ex;
        }
        acc.x *= invh; acc.y *= invh; acc.z *= invh; acc.w *= invh;
    } else {
        float mx[H];
#pragma unroll
        for (int h = 0; h < H; h++) mx[h] = -3.0e38f;
        for (int e = start + lane; e < end; e += 32) {
            int s = srcs[e];
#pragma unroll
            for (int h = 0; h < H; h++) {
                float v = a_s[s * H + h] + adh[h];
                v = v > 0.f ? v : 0.2f * v;
                mx[h] = fmaxf(mx[h], v);
            }
        }
#pragma unroll
        for (int h = 0; h < H; h++) mx[h] = warpMax(mx[h]);
        float sm[H];
#pragma unroll
        for (int h = 0; h < H; h++) sm[h] = 0.f;
        for (int e = start + lane; e < end; e += 32) {
            int s = srcs[e];
#pragma unroll
            for (int h = 0; h < H; h++) {
                float v = a_s[s * H + h] + adh[h];
                v = v > 0.f ? v : 0.2f * v;
                sm[h] += __expf(v - mx[h]);
            }
        }
#pragma unroll
        for (int h = 0; h < H; h++) sm[h] = warpSum(sm[h]);
        float invh;
        if (H == 1) invh = 1.f / (sm[0] + 1e-16f);
        else invh = 1.f / ((hh == 0 ? sm[0] : hh == 1 ? sm[1] : hh == 2 ? sm[2] : sm[3]) + 1e-16f);
        float mxh = (H == 1) ? mx[0] : (hh == 0 ? mx[0] : hh == 1 ? mx[1] : hh == 2 ? mx[2] : mx[3]);
        float adhh = (H == 1) ? adh[0] : (hh == 0 ? adh[0] : hh == 1 ? adh[1] : hh == 2 ? adh[2] : adh[3]);
        for (int e = start; e < end; e++) {
            int s = srcs[e];
            float v = a_s[s * H + hh] + adhh;
            v = v > 0.f ? v : 0.2f * v;
            float ex = __expf(v - mxh);
            float4 t = *(const float4*)(tS + (size_t)s * 128 + lane * 4);
            acc.x += t.x * ex;
            acc.y += t.y * ex;
            acc.z += t.z * ex;
            acc.w += t.w * ex;
        }
        acc.x *= invh; acc.y *= invh; acc.z *= invh; acc.w *= invh;
    }
    *(float4*)(outp + (size_t)wid * 128 + lane * 4) = acc;
}

// ---------------------------------------------------------------------------
// fused: h_out = relu(LN(n + bias) * g + b) + h_prev   (warp per node)
// ---------------------------------------------------------------------------
__global__ void ln_relu_residual(const float* __restrict__ nbuf, const float* __restrict__ bias,
                                 const float* __restrict__ gamma, const float* __restrict__ beta,
                                 const float* __restrict__ hprev, float* __restrict__ hout,
                                 int N) {
    int wid = (blockIdx.x * blockDim.x + threadIdx.x) >> 5;
    int lane = threadIdx.x & 31;
    if (wid >= N) return;
    size_t base = (size_t)wid * 128 + lane * 4;
    float4 v = *(const float4*)(nbuf + base);
    float4 bb = *(const float4*)(bias + lane * 4);
    v.x += bb.x; v.y += bb.y; v.z += bb.z; v.w += bb.w;
    float mu = warpSum(v.x + v.y + v.z + v.w) * (1.f / 128.f);
    float dx = v.x - mu, dy = v.y - mu, dz = v.z - mu, dw = v.w - mu;
    float var = warpSum(dx * dx + dy * dy + dz * dz + dw * dw) * (1.f / 128.f);
    float r = rsqrtf(var + 1e-5f);
    float4 g = *(const float4*)(gamma + lane * 4);
    float4 b = *(const float4*)(beta + lane * 4);
    float4 hp = *(const float4*)(hprev + base);
    float4 o;
    o.x = fmaxf(0.f, dx * r * g.x + b.x) + hp.x;
    o.y = fmaxf(0.f, dy * r * g.y + b.y) + hp.y;
    o.z = fmaxf(0.f, dz * r * g.z + b.z) + hp.z;
    o.w = fmaxf(0.f, dw * r * g.w + b.w) + hp.w;
    *(float4*)(hout + base) = o;
}

// ---------------------------------------------------------------------------
static inline void* sym(const void* s) {
    void* p = nullptr;
    cudaGetSymbolAddress(&p, s);
    return p;
}

extern "C" void kernel_launch(void* const* d_in, const int* in_sizes, int n_in,
                              void* d_out, int out_size) {
    const float* x_A = (const float*)d_in[0];
    const float* x_B = (const float*)d_in[1];
    const float* pWA = (const float*)d_in[2];
    const float* pbA = (const float*)d_in[3];
    const float* pWB = (const float*)d_in[4];
    const float* pbB = (const float*)d_in[5];
    const float* w0ab = (const float*)d_in[6];
    const float* as0ab = (const float*)d_in[7];
    const float* ad0ab = (const float*)d_in[8];
    const float* b0ab = (const float*)d_in[9];
    const float* w0ba = (const float*)d_in[10];
    const float* as0ba = (const float*)d_in[11];
    const float* ad0ba = (const float*)d_in[12];
    const float* b0ba = (const float*)d_in[13];
    const float* w1ab = (const float*)d_in[14];
    const float* as1ab = (const float*)d_in[15];
    const float* ad1ab = (const float*)d_in[16];
    const float* b1ab = (const float*)d_in[17];
    const float* w1ba = (const float*)d_in[18];
    const float* as1ba = (const float*)d_in[19];
    const float* ad1ba = (const float*)d_in[20];
    const float* b1ba = (const float*)d_in[21];
    const float* g0A = (const float*)d_in[22];
    const float* bn0A = (const float*)d_in[23];
    const float* g0B = (const float*)d_in[24];
    const float* bn0B = (const float*)d_in[25];
    const float* g1A = (const float*)d_in[26];
    const float* bn1A = (const float*)d_in[27];
    const float* g1B = (const float*)d_in[28];
    const float* bn1B = (const float*)d_in[29];
    const int* ei_AB = (const int*)d_in[30];
    const int* ei_BA = (const int*)d_in[31];

    const int NA = in_sizes[0] / 128;
    const int NB = in_sizes[1] / 64;
    const int E = in_sizes[30] / 2;

    float* hA = (float*)sym(g_hA);
    float* hB = (float*)sym(g_hB);
    float* nA = (float*)sym(g_nA);
    float* nB = (float*)sym(g_nB);
    float* t1 = (float*)sym(g_t1);
    float* t2 = (float*)sym(g_t2);
    float* as1 = (float*)sym(g_as1);
    float* ad1 = (float*)sym(g_ad1);
    float* as2 = (float*)sym(g_as2);
    float* ad2 = (float*)sym(g_ad2);
    float* wpS1 = (float*)sym(g_wpS1);
    float* wpD1 = (float*)sym(g_wpD1);
    float* wpS2 = (float*)sym(g_wpS2);
    float* wpD2 = (float*)sym(g_wpD2);
    int* rpAB = (int*)sym(g_rpAB);
    int* rpBA = (int*)sym(g_rpBA);
    int* cur = (int*)sym(g_cur);
    int* deg = (int*)sym(g_deg);
    int* srcAB = (int*)sym(g_srcAB);
    int* srcBA = (int*)sym(g_srcBA);

    const int TB = 256;
    const int eb = (E + TB - 1) / TB;
    const int wbA = (NA * 32 + TB - 1) / TB;
    const int wbB = (NB * 32 + TB - 1) / TB;
    const int gbA = (NA + 127) / 128;
    const int gbB = (NB + 127) / 128;

    // --- CSR for AB (launches 1-4), then memset (5), then the big GEMM at
    //     launch slot 6 so ncu (-s 5 -c 1) profiles it next round ---
    cudaMemsetAsync(deg, 0, NB * sizeof(int));
    edge_hist<<<eb, TB>>>(ei_AB + E, deg, E);
    exscan_block<<<1, 256>>>(deg, rpAB, cur, NB);
    edge_fill<<<eb, TB>>>(ei_AB, ei_AB + E, cur, srcAB, E);
    cudaMemsetAsync(deg, 0, NA * sizeof(int));

    gemm_bf16s3_128<<<gbA, TB>>>(x_A, pWA, pbA, hA, NA, 128);   // launch #6

    edge_hist<<<eb, TB>>>(ei_BA + E, deg, E);
    exscan_block<<<1, 256>>>(deg, rpBA, cur, NA);
    edge_fill<<<eb, TB>>>(ei_BA, ei_BA + E, cur, srcBA, E);

    gemm_bf16s3_128<<<gbB, TB>>>(x_B, pWB, pbB, hB, NB, 64);

    // ================= layer 0 (H=4, D=32) =================
    make_wp<4><<<1, 128>>>(w0ab, as0ab, ad0ab, wpS1, wpD1);
    make_wp<4><<<1, 128>>>(w0ba, as0ba, ad0ba, wpS2, wpD2);

    gemm_bf16s3_128<<<gbA, TB>>>(hA, w0ab, nullptr, t1, NA, 128);
    gemm_bf16s3_128<<<gbB, TB>>>(hB, w0ba, nullptr, t2, NB, 128);

    node_scores2<4><<<wbA, TB>>>(hA, wpS1, wpD2, as1, ad2, NA);  // A: src(AB), dst(BA)
    node_scores2<4><<<wbB, TB>>>(hB, wpS2, wpD1, as2, ad1, NB);  // B: src(BA), dst(AB)

    gat_aggregate<4><<<wbB, TB>>>(rpAB, srcAB, as1, ad1, t1, nB, NB);
    gat_aggregate<4><<<wbA, TB>>>(rpBA, srcBA, as2, ad2, t2, nA, NA);

    ln_relu_residual<<<wbA, TB>>>(nA, b0ba, g0A, bn0A, hA, hA, NA);
    ln_relu_residual<<<wbB, TB>>>(nB, b0ab, g0B, bn0B, hB, hB, NB);

    // ================= layer 1 (H=1, D=128) =================
    make_wp<1><<<1, 128>>>(w1ab, as1ab, ad1ab, wpS1, wpD1);
    make_wp<1><<<1, 128>>>(w1ba, as1ba, ad1ba, wpS2, wpD2);

    gemm_bf16s3_128<<<gbA, TB>>>(hA, w1ab, nullptr, t1, NA, 128);
    gemm_bf16s3_128<<<gbB, TB>>>(hB, w1ba, nullptr, t2, NB, 128);

    node_scores2<1><<<wbA, TB>>>(hA, wpS1, wpD2, as1, ad2, NA);
    node_scores2<1><<<wbB, TB>>>(hB, wpS2, wpD1, as2, ad1, NB);

    gat_aggregate<1><<<wbB, TB>>>(rpAB, srcAB, as1, ad1, t1, nB, NB);
    gat_aggregate<1><<<wbA, TB>>>(rpBA, srcBA, as2, ad2, t2, nA, NA);

    float* outA = (float*)d_out;
    float* outB = outA + (size_t)NA * 128;
    ln_relu_residual<<<wbA, TB>>>(nA, b1ba, g1A, bn1A, hA, outA, NA);
    ln_relu_residual<<<wbB, TB>>>(nB, b1ab, g1B, bn1B, hB, outB, NB);
}

// round 6
// speedup vs baseline: 1.3725x; 1.0938x over previous
#include <cuda_runtime.h>
#include <cuda_bf16.h>
#include <mma.h>
#include <math.h>

using namespace nvcuda;

// ---------------------------------------------------------------------------
// HeteroGAT encoder.
//   - 6 GEMMs via bf16 split-3 WMMA, persistent-CTA grid (no wave tail)
//   - CSR-by-dst; fused aggregate + softmax + LN + relu + residual
//     (+ next-layer scores fused into layer-0 epilogue)
//   - all 4 attention-weight projections in one coalesced kernel
// ---------------------------------------------------------------------------

#define NMAX 50176   // multiple of 128
#define EMAX 500000

__device__ float g_hA[NMAX * 128];
__device__ float g_hB[NMAX * 128];
__device__ float g_t1[NMAX * 128];
__device__ float g_t2[NMAX * 128];
__device__ float g_as1[NMAX], g_ad1[NMAX * 4];   // layer0 uses *4; layer1 scalar
__device__ float g_as1_0[NMAX * 4], g_ad1_0[NMAX * 4];
__device__ float g_as2_0[NMAX * 4], g_ad2_0[NMAX * 4];
__device__ float g_as1_1[NMAX], g_ad1_1[NMAX];
__device__ float g_as2_1[NMAX], g_ad2_1[NMAX];
__device__ float g_wp[8][128 * 4];   // [cfg*2+{S,D}] packed: see make_wp_all
__device__ int g_rpAB[NMAX + 1], g_rpBA[NMAX + 1];
__device__ int g_cur[NMAX], g_deg[NMAX];
__device__ int g_srcAB[EMAX], g_srcBA[EMAX];

__device__ __forceinline__ float warpSum(float v) {
#pragma unroll
    for (int o = 16; o > 0; o >>= 1) v += __shfl_xor_sync(0xffffffffu, v, o);
    return v;
}
__device__ __forceinline__ float warpMax(float v) {
#pragma unroll
    for (int o = 16; o > 0; o >>= 1) v = fmaxf(v, __shfl_xor_sync(0xffffffffu, v, o));
    return v;
}

// ---------------------------------------------------------------------------
// bf16 split-3 WMMA GEMM, persistent CTAs.
// out[M,128] = X[M,K] @ W[K,128] (+ bias). K in {64,128}. out NMAX-padded.
// ---------------------------------------------------------------------------
#define XA_LD 40
#define WB_LD 136
#define BS_LD 136

__global__ __launch_bounds__(256) void gemm_bf16s3_128(
    const float* __restrict__ X, const float* __restrict__ W,
    const float* __restrict__ bias, float* __restrict__ out, int M, int K) {
    __shared__ __nv_bfloat16 Xhi[128][XA_LD];
    __shared__ __nv_bfloat16 Xlo[128][XA_LD];
    __shared__ __nv_bfloat16 Whi[32][WB_LD];
    __shared__ __nv_bfloat16 Wlo[32][WB_LD];
    __shared__ float Bs[16][BS_LD];

    const int tid = threadIdx.x;
    const int wid = tid >> 5;
    const int warp_row = (wid >> 1) * 32;
    const int warp_col = (wid & 1) * 64;

    if (bias) {
#pragma unroll
        for (int i = tid; i < 16 * 128; i += 256) Bs[i >> 7][i & 127] = bias[i & 127];
        __syncthreads();
    }

    const int nTiles = (M + 127) >> 7;
    for (int t = blockIdx.x; t < nTiles; t += gridDim.x) {
        const int block_row = t * 128;

        wmma::fragment<wmma::accumulator, 16, 16, 16, float> acc[2][4];
#pragma unroll
        for (int i = 0; i < 2; i++)
#pragma unroll
            for (int j = 0; j < 4; j++) {
                if (bias)
                    wmma::load_matrix_sync(acc[i][j], &Bs[0][warp_col + j * 16], BS_LD,
                                           wmma::mem_row_major);
                else
                    wmma::fill_fragment(acc[i][j], 0.f);
            }

        for (int k0 = 0; k0 < K; k0 += 32) {
#pragma unroll
            for (int p = 0; p < 4; p++) {
                int idx = tid + p * 256;
                int r = idx >> 3;
                int c4 = (idx & 7) * 4;
                int gr = block_row + r;
                float4 v = make_float4(0.f, 0.f, 0.f, 0.f);
                if (gr < M) v = *(const float4*)&X[(size_t)gr * K + k0 + c4];
                float vv[4] = {v.x, v.y, v.z, v.w};
#pragma unroll
                for (int q = 0; q < 4; q++) {
                    __nv_bfloat16 hi = __float2bfloat16(vv[q]);
                    __nv_bfloat16 lo = __float2bfloat16(vv[q] - __bfloat162float(hi));
                    Xhi[r][c4 + q] = hi;
                    Xlo[r][c4 + q] = lo;
                }
            }
#pragma unroll
            for (int p = 0; p < 4; p++) {
                int idx = tid + p * 256;
                int r = idx >> 5;
                int c4 = (idx & 31) * 4;
                float4 v = *(const float4*)&W[(size_t)(k0 + r) * 128 + c4];
                float vv[4] = {v.x, v.y, v.z, v.w};
#pragma unroll
                for (int q = 0; q < 4; q++) {
                    __nv_bfloat16 hi = __float2bfloat16(vv[q]);
                    __nv_bfloat16 lo = __float2bfloat16(vv[q] - __bfloat162float(hi));
                    Whi[r][c4 + q] = hi;
                    Wlo[r][c4 + q] = lo;
                }
            }
            __syncthreads();

#pragma unroll
            for (int ks = 0; ks < 32; ks += 16) {
                wmma::fragment<wmma::matrix_a, 16, 16, 16, __nv_bfloat16, wmma::row_major> ahi[2], alo[2];
                wmma::fragment<wmma::matrix_b, 16, 16, 16, __nv_bfloat16, wmma::row_major> bhi[4], blo[4];
#pragma unroll
                for (int i = 0; i < 2; i++) {
                    wmma::load_matrix_sync(ahi[i], &Xhi[warp_row + i * 16][ks], XA_LD);
                    wmma::load_matrix_sync(alo[i], &Xlo[warp_row + i * 16][ks], XA_LD);
                }
#pragma unroll
                for (int j = 0; j < 4; j++) {
                    wmma::load_matrix_sync(bhi[j], &Whi[ks][warp_col + j * 16], WB_LD);
                    wmma::load_matrix_sync(blo[j], &Wlo[ks][warp_col + j * 16], WB_LD);
                }
#pragma unroll
                for (int i = 0; i < 2; i++)
#pragma unroll
                    for (int j = 0; j < 4; j++) {
                        wmma::mma_sync(acc[i][j], ahi[i], blo[j], acc[i][j]);
                        wmma::mma_sync(acc[i][j], alo[i], bhi[j], acc[i][j]);
                        wmma::mma_sync(acc[i][j], ahi[i], bhi[j], acc[i][j]);
                    }
            }
            __syncthreads();
        }

#pragma unroll
        for (int i = 0; i < 2; i++)
#pragma unroll
            for (int j = 0; j < 4; j++) {
                size_t off = (size_t)(block_row + warp_row + i * 16) * 128 + warp_col + j * 16;
                wmma::store_matrix_sync(&out[off], acc[i][j], 128, wmma::mem_row_major);
            }
    }
}

// ---------------------------------------------------------------------------
// all 4 attention-weight projections, one launch, coalesced via smem.
// cfg 0: w0ab H=4 -> wp[0](S),wp[1](D)   cfg 1: w0ba H=4 -> wp[2],wp[3]
// cfg 2: w1ab H=1 -> wp[4],wp[5]         cfg 3: w1ba H=1 -> wp[6],wp[7]
// ---------------------------------------------------------------------------
__global__ void make_wp_all(
    const float* __restrict__ w0ab, const float* __restrict__ as0ab, const float* __restrict__ ad0ab,
    const float* __restrict__ w0ba, const float* __restrict__ as0ba, const float* __restrict__ ad0ba,
    const float* __restrict__ w1ab, const float* __restrict__ as1ab, const float* __restrict__ ad1ab,
    const float* __restrict__ w1ba, const float* __restrict__ as1ba, const float* __restrict__ ad1ba) {
    __shared__ float Ws[64][129];
    int cfg = blockIdx.x;
    const float* W = cfg == 0 ? w0ab : cfg == 1 ? w0ba : cfg == 2 ? w1ab : w1ba;
    const float* avs = cfg == 0 ? as0ab : cfg == 1 ? as0ba : cfg == 2 ? as1ab : as1ba;
    const float* avd = cfg == 0 ? ad0ab : cfg == 1 ? ad0ba : cfg == 2 ? ad1ab : ad1ba;
    const int H = (cfg < 2) ? 4 : 1;
    const int D = 128 / H;
    float* wpS = g_wp[cfg * 2];
    float* wpD = g_wp[cfg * 2 + 1];

    int tid = threadIdx.x;   // 256 threads
    float ss[4] = {0.f, 0.f, 0.f, 0.f}, sd[4] = {0.f, 0.f, 0.f, 0.f};
    for (int chunk = 0; chunk < 2; chunk++) {
        int r0 = chunk * 64;
        for (int i = tid; i < 64 * 128; i += 256)
            Ws[i >> 7][i & 127] = W[(size_t)(r0 + (i >> 7)) * 128 + (i & 127)];
        __syncthreads();
        int k = tid;  // threads 0..127 own output row k
        if (k < 128 && k >= r0 && k < r0 + 64) {
            for (int h = 0; h < H; h++) {
                float a = 0.f, b = 0.f;
                for (int d = 0; d < D; d++) {
                    float w = Ws[k - r0][h * D + d];
                    a += w * avs[h * D + d];
                    b += w * avd[h * D + d];
                }
                ss[h] = a; sd[h] = b;
            }
        }
        __syncthreads();
    }
    if (tid < 128)
        for (int h = 0; h < H; h++) { wpS[tid * H + h] = ss[h]; wpD[tid * H + h] = sd[h]; }
}

// ---------------------------------------------------------------------------
// fused node scores (layer 0 only): read X once, emit src+dst scores
// ---------------------------------------------------------------------------
template <int H>
__global__ void node_scores2(const float* __restrict__ X, const float* __restrict__ wpS,
                             const float* __restrict__ wpD, float* __restrict__ outS,
                             float* __restrict__ outD, int N) {
    int w = (blockIdx.x * blockDim.x + threadIdx.x) >> 5;
    int lane = threadIdx.x & 31;
    if (w >= N) return;
    const float* xr = X + (size_t)w * 128;
    float accS[H], accD[H];
#pragma unroll
    for (int h = 0; h < H; h++) { accS[h] = 0.f; accD[h] = 0.f; }
#pragma unroll
    for (int kk = 0; kk < 4; kk++) {
        int k = lane + kk * 32;
        float x = xr[k];
#pragma unroll
        for (int h = 0; h < H; h++) {
            accS[h] += x * wpS[k * H + h];
            accD[h] += x * wpD[k * H + h];
        }
    }
#pragma unroll
    for (int h = 0; h < H; h++) { accS[h] = warpSum(accS[h]); accD[h] = warpSum(accD[h]); }
    if (lane == 0) {
#pragma unroll
        for (int h = 0; h < H; h++) { outS[w * H + h] = accS[h]; outD[w * H + h] = accD[h]; }
    }
}

// ---------------------------------------------------------------------------
// CSR build
// ---------------------------------------------------------------------------
__global__ void edge_hist(const int* __restrict__ dst, int* __restrict__ deg, int E) {
    int e = blockIdx.x * blockDim.x + threadIdx.x;
    if (e < E) atomicAdd(&deg[dst[e]], 1);
}
__global__ void edge_fill(const int* __restrict__ src, const int* __restrict__ dst,
                          int* __restrict__ cursor, int* __restrict__ col, int E) {
    int e = blockIdx.x * blockDim.x + threadIdx.x;
    if (e < E) {
        int p = atomicAdd(&cursor[dst[e]], 1);
        col[p] = src[e];
    }
}
__global__ __launch_bounds__(1024) void exscan_block(
    const int* __restrict__ deg, int* __restrict__ rowptr, int* __restrict__ cursor, int N) {
    __shared__ int sums[1024];
    int t = threadIdx.x;
    int chunk = (N + 1023) / 1024;
    int b0 = t * chunk;
    int b1 = min(b0 + chunk, N);
    int s = 0;
    for (int i = b0; i < b1; i++) s += deg[i];
    sums[t] = s;
    __syncthreads();
    for (int off = 1; off < 1024; off <<= 1) {
        int v = (t >= off) ? sums[t - off] : 0;
        __syncthreads();
        sums[t] += v;
        __syncthreads();
    }
    int run = (t == 0) ? 0 : sums[t - 1];
    for (int i = b0; i < b1; i++) {
        rowptr[i] = run;
        cursor[i] = run;
        run += deg[i];
    }
    if (t == 1023) rowptr[N] = run;
}

// ---------------------------------------------------------------------------
// fused GAT aggregate + softmax + bias + LN + relu + residual
//   (+ optionally next-layer H=1 scores). Warp per destination node.
// ---------------------------------------------------------------------------
template <int H, bool SC>
__global__ __launch_bounds__(256) void gat_fused(
    const int* __restrict__ rowptr, const int* __restrict__ srcs,
    const float* __restrict__ a_s, const float* __restrict__ a_d,
    const float* __restrict__ tS, const float* __restrict__ gbias,
    const float* __restrict__ gamma, const float* __restrict__ beta,
    const float* __restrict__ hprev, float* __restrict__ hout,
    const float* __restrict__ wpSn, const float* __restrict__ wpDn,
    float* __restrict__ outSn, float* __restrict__ outDn, int Ndst) {
    const int D = 128 / H;
    const int CAP = 128;
    __shared__ float s_ex[8][CAP * H];
    __shared__ int s_src[8][CAP];

    int wid = (blockIdx.x * blockDim.x + threadIdx.x) >> 5;
    int w = threadIdx.x >> 5;
    int lane = threadIdx.x & 31;
    if (wid >= Ndst) return;
    int start = rowptr[wid];
    int end = rowptr[wid + 1];
    int deg = end - start;

    float adh[H];
#pragma unroll
    for (int h = 0; h < H; h++) adh[h] = a_d[wid * H + h];

    const int hh = (lane * 4) / D;
    float4 acc = make_float4(0.f, 0.f, 0.f, 0.f);

    if (deg <= CAP) {
        float sc[4][H];
        int nIt = (deg + 31) >> 5;
        float mx[H];
#pragma unroll
        for (int h = 0; h < H; h++) mx[h] = -3.0e38f;
#pragma unroll
        for (int i = 0; i < 4; i++) {
            int j = lane + i * 32;
            if (i < nIt && j < deg) {
                int s = srcs[start + j];
                s_src[w][j] = s;
#pragma unroll
                for (int h = 0; h < H; h++) {
                    float v = a_s[s * H + h] + adh[h];
                    v = v > 0.f ? v : 0.2f * v;
                    sc[i][h] = v;
                    mx[h] = fmaxf(mx[h], v);
                }
            }
        }
#pragma unroll
        for (int h = 0; h < H; h++) mx[h] = warpMax(mx[h]);

        float sm[H];
#pragma unroll
        for (int h = 0; h < H; h++) sm[h] = 0.f;
#pragma unroll
        for (int i = 0; i < 4; i++) {
            int j = lane + i * 32;
            if (i < nIt && j < deg) {
#pragma unroll
                for (int h = 0; h < H; h++) {
                    float ex = __expf(sc[i][h] - mx[h]);
                    sm[h] += ex;
                    s_ex[w][j * H + h] = ex;
                }
            }
        }
#pragma unroll
        for (int h = 0; h < H; h++) sm[h] = warpSum(sm[h]);
        float invh;
        if (H == 1) invh = 1.f / (sm[0] + 1e-16f);
        else invh = 1.f / ((hh == 0 ? sm[0] : hh == 1 ? sm[1] : hh == 2 ? sm[2] : sm[3]) + 1e-16f);

        __syncwarp();
        // phase C: unroll x4 for MLP
        int e = 0;
        const float* base = tS;
        for (; e + 4 <= deg; e += 4) {
            float ex0 = s_ex[w][(e + 0) * H + hh];
            float ex1 = s_ex[w][(e + 1) * H + hh];
            float ex2 = s_ex[w][(e + 2) * H + hh];
            float ex3 = s_ex[w][(e + 3) * H + hh];
            int s0 = s_src[w][e + 0], s1 = s_src[w][e + 1];
            int s2 = s_src[w][e + 2], s3 = s_src[w][e + 3];
            float4 v0 = *(const float4*)(base + (size_t)s0 * 128 + lane * 4);
            float4 v1 = *(const float4*)(base + (size_t)s1 * 128 + lane * 4);
            float4 v2 = *(const float4*)(base + (size_t)s2 * 128 + lane * 4);
            float4 v3 = *(const float4*)(base + (size_t)s3 * 128 + lane * 4);
            acc.x += v0.x * ex0 + v1.x * ex1 + v2.x * ex2 + v3.x * ex3;
            acc.y += v0.y * ex0 + v1.y * ex1 + v2.y * ex2 + v3.y * ex3;
            acc.z += v0.z * ex0 + v1.z * ex1 + v2.z * ex2 + v3.z * ex3;
            acc.w += v0.w * ex0 + v1.w * ex1 + v2.w * ex2 + v3.w * ex3;
        }
        for (; e < deg; e++) {
            float ex = s_ex[w][e * H + hh];
            int s = s_src[w][e];
            float4 v = *(const float4*)(base + (size_t)s * 128 + lane * 4);
            acc.x += v.x * ex; acc.y += v.y * ex; acc.z += v.z * ex; acc.w += v.w * ex;
        }
        acc.x *= invh; acc.y *= invh; acc.z *= invh; acc.w *= invh;
    } else {
        float mx[H];
#pragma unroll
        for (int h = 0; h < H; h++) mx[h] = -3.0e38f;
        for (int e = start + lane; e < end; e += 32) {
            int s = srcs[e];
#pragma unroll
            for (int h = 0; h < H; h++) {
                float v = a_s[s * H + h] + adh[h];
                v = v > 0.f ? v : 0.2f * v;
                mx[h] = fmaxf(mx[h], v);
            }
        }
#pragma unroll
        for (int h = 0; h < H; h++) mx[h] = warpMax(mx[h]);
        float sm[H];
#pragma unroll
        for (int h = 0; h < H; h++) sm[h] = 0.f;
        for (int e = start + lane; e < end; e += 32) {
            int s = srcs[e];
#pragma unroll
            for (int h = 0; h < H; h++) {
                float v = a_s[s * H + h] + adh[h];
                v = v > 0.f ? v : 0.2f * v;
                sm[h] += __expf(v - mx[h]);
            }
        }
#pragma unroll
        for (int h = 0; h < H; h++) sm[h] = warpSum(sm[h]);
        float invh;
        if (H == 1) invh = 1.f / (sm[0] + 1e-16f);
        else invh = 1.f / ((hh == 0 ? sm[0] : hh == 1 ? sm[1] : hh == 2 ? sm[2] : sm[3]) + 1e-16f);
        float mxh = (H == 1) ? mx[0] : (hh == 0 ? mx[0] : hh == 1 ? mx[1] : hh == 2 ? mx[2] : mx[3]);
        float adhh = (H == 1) ? adh[0] : (hh == 0 ? adh[0] : hh == 1 ? adh[1] : hh == 2 ? adh[2] : adh[3]);
        for (int e = start; e < end; e++) {
            int s = srcs[e];
            float v = a_s[s * H + hh] + adhh;
            v = v > 0.f ? v : 0.2f * v;
            float ex = __expf(v - mxh);
            float4 t = *(const float4*)(tS + (size_t)s * 128 + lane * 4);
            acc.x += t.x * ex; acc.y += t.y * ex; acc.z += t.z * ex; acc.w += t.w * ex;
        }
        acc.x *= invh; acc.y *= invh; acc.z *= invh; acc.w *= invh;
    }

    // epilogue: + gat bias, LN, relu, + residual
    size_t rbase = (size_t)wid * 128 + lane * 4;
    float4 bb = *(const float4*)(gbias + lane * 4);
    acc.x += bb.x; acc.y += bb.y; acc.z += bb.z; acc.w += bb.w;
    float mu = warpSum(acc.x + acc.y + acc.z + acc.w) * (1.f / 128.f);
    float dx = acc.x - mu, dy = acc.y - mu, dz = acc.z - mu, dw = acc.w - mu;
    float var = warpSum(dx * dx + dy * dy + dz * dz + dw * dw) * (1.f / 128.f);
    float r = rsqrtf(var + 1e-5f);
    float4 gg = *(const float4*)(gamma + lane * 4);
    float4 be = *(const float4*)(beta + lane * 4);
    float4 hp = *(const float4*)(hprev + rbase);
    float4 o;
    o.x = fmaxf(0.f, dx * r * gg.x + be.x) + hp.x;
    o.y = fmaxf(0.f, dy * r * gg.y + be.y) + hp.y;
    o.z = fmaxf(0.f, dz * r * gg.z + be.z) + hp.z;
    o.w = fmaxf(0.f, dw * r * gg.w + be.w) + hp.w;
    *(float4*)(hout + rbase) = o;

    if (SC) {  // next-layer H=1 scores from the freshly computed row
        float4 ws = *(const float4*)(wpSn + lane * 4);
        float4 wd = *(const float4*)(wpDn + lane * 4);
        float sS = o.x * ws.x + o.y * ws.y + o.z * ws.z + o.w * ws.w;
        float sD = o.x * wd.x + o.y * wd.y + o.z * wd.z + o.w * wd.w;
        sS = warpSum(sS);
        sD = warpSum(sD);
        if (lane == 0) { outSn[wid] = sS; outDn[wid] = sD; }
    }
}

// ---------------------------------------------------------------------------
static inline void* sym(const void* s) {
    void* p = nullptr;
    cudaGetSymbolAddress(&p, s);
    return p;
}

extern "C" void kernel_launch(void* const* d_in, const int* in_sizes, int n_in,
                              void* d_out, int out_size) {
    const float* x_A = (const float*)d_in[0];
    const float* x_B = (const float*)d_in[1];
    const float* pWA = (const float*)d_in[2];
    const float* pbA = (const float*)d_in[3];
    const float* pWB = (const float*)d_in[4];
    const float* pbB = (const float*)d_in[5];
    const float* w0ab = (const float*)d_in[6];
    const float* as0ab = (const float*)d_in[7];
    const float* ad0ab = (const float*)d_in[8];
    const float* b0ab = (const float*)d_in[9];
    const float* w0ba = (const float*)d_in[10];
    const float* as0ba = (const float*)d_in[11];
    const float* ad0ba = (const float*)d_in[12];
    const float* b0ba = (const float*)d_in[13];
    const float* w1ab = (const float*)d_in[14];
    const float* as1ab = (const float*)d_in[15];
    const float* ad1ab = (const float*)d_in[16];
    const float* b1ab = (const float*)d_in[17];
    const float* w1ba = (const float*)d_in[18];
    const float* as1ba = (const float*)d_in[19];
    const float* ad1ba = (const float*)d_in[20];
    const float* b1ba = (const float*)d_in[21];
    const float* g0A = (const float*)d_in[22];
    const float* bn0A = (const float*)d_in[23];
    const float* g0B = (const float*)d_in[24];
    const float* bn0B = (const float*)d_in[25];
    const float* g1A = (const float*)d_in[26];
    const float* bn1A = (const float*)d_in[27];
    const float* g1B = (const float*)d_in[28];
    const float* bn1B = (const float*)d_in[29];
    const int* ei_AB = (const int*)d_in[30];
    const int* ei_BA = (const int*)d_in[31];

    const int NA = in_sizes[0] / 128;
    const int NB = in_sizes[1] / 64;
    const int E = in_sizes[30] / 2;

    float* hA = (float*)sym(g_hA);
    float* hB = (float*)sym(g_hB);
    float* t1 = (float*)sym(g_t1);
    float* t2 = (float*)sym(g_t2);
    float* as1_0 = (float*)sym(g_as1_0);
    float* ad1_0 = (float*)sym(g_ad1_0);
    float* as2_0 = (float*)sym(g_as2_0);
    float* ad2_0 = (float*)sym(g_ad2_0);
    float* as1_1 = (float*)sym(g_as1_1);
    float* ad1_1 = (float*)sym(g_ad1_1);
    float* as2_1 = (float*)sym(g_as2_1);
    float* ad2_1 = (float*)sym(g_ad2_1);
    float* wp = (float*)sym(g_wp);     // 8 slabs of 512 floats
    int* rpAB = (int*)sym(g_rpAB);
    int* rpBA = (int*)sym(g_rpBA);
    int* cur = (int*)sym(g_cur);
    int* deg = (int*)sym(g_deg);
    int* srcAB = (int*)sym(g_srcAB);
    int* srcBA = (int*)sym(g_srcBA);

    float* wpS1_0 = wp + 0 * 512, *wpD1_0 = wp + 1 * 512;
    float* wpS2_0 = wp + 2 * 512, *wpD2_0 = wp + 3 * 512;
    float* wpS1_1 = wp + 4 * 512, *wpD1_1 = wp + 5 * 512;
    float* wpS2_1 = wp + 6 * 512, *wpD2_1 = wp + 7 * 512;

    const int TB = 256;
    const int eb = (E + TB - 1) / TB;
    const int wbA = (NA * 32 + TB - 1) / TB;
    const int wbB = (NB * 32 + TB - 1) / TB;
    const int PG = 148;   // persistent GEMM grid

    // launches 1-5, then big GEMM at slot 6 for ncu
    cudaMemsetAsync(deg, 0, NB * sizeof(int));
    edge_hist<<<eb, TB>>>(ei_AB + E, deg, E);
    exscan_block<<<1, 1024>>>(deg, rpAB, cur, NB);
    edge_fill<<<eb, TB>>>(ei_AB, ei_AB + E, cur, srcAB, E);
    cudaMemsetAsync(deg, 0, NA * sizeof(int));

    gemm_bf16s3_128<<<PG, TB>>>(x_A, pWA, pbA, hA, NA, 128);   // launch #6

    edge_hist<<<eb, TB>>>(ei_BA + E, deg, E);
    exscan_block<<<1, 1024>>>(deg, rpBA, cur, NA);
    edge_fill<<<eb, TB>>>(ei_BA, ei_BA + E, cur, srcBA, E);

    gemm_bf16s3_128<<<PG, TB>>>(x_B, pWB, pbB, hB, NB, 64);
    make_wp_all<<<4, 256>>>(w0ab, as0ab, ad0ab, w0ba, as0ba, ad0ba,
                            w1ab, as1ab, ad1ab, w1ba, as1ba, ad1ba);

    // ================= layer 0 (H=4) =================
    gemm_bf16s3_128<<<PG, TB>>>(hA, w0ab, nullptr, t1, NA, 128);
    gemm_bf16s3_128<<<PG, TB>>>(hB, w0ba, nullptr, t2, NB, 128);

    node_scores2<4><<<wbA, TB>>>(hA, wpS1_0, wpD2_0, as1_0, ad2_0, NA);
    node_scores2<4><<<wbB, TB>>>(hB, wpS2_0, wpD1_0, as2_0, ad1_0, NB);

    // AB: dst B -> writes hB + layer1 scores for B (src of BA, dst of AB)
    gat_fused<4, true><<<wbB, TB>>>(rpAB, srcAB, as1_0, ad1_0, t1, b0ab,
                                    g0B, bn0B, hB, hB,
                                    wpS2_1, wpD1_1, as2_1, ad1_1, NB);
    // BA: dst A -> writes hA + layer1 scores for A
    gat_fused<4, true><<<wbA, TB>>>(rpBA, srcBA, as2_0, ad2_0, t2, b0ba,
                                    g0A, bn0A, hA, hA,
                                    wpS1_1, wpD2_1, as1_1, ad2_1, NA);

    // ================= layer 1 (H=1) =================
    gemm_bf16s3_128<<<PG, TB>>>(hA, w1ab, nullptr, t1, NA, 128);
    gemm_bf16s3_128<<<PG, TB>>>(hB, w1ba, nullptr, t2, NB, 128);

    float* outA = (float*)d_out;
    float* outB = outA + (size_t)NA * 128;
    gat_fused<1, false><<<wbB, TB>>>(rpAB, srcAB, as1_1, ad1_1, t1, b1ab,
                                     g1B, bn1B, hB, outB,
                                     nullptr, nullptr, nullptr, nullptr, NB);
    gat_fused<1, false><<<wbA, TB>>>(rpBA, srcBA, as2_1, ad2_1, t2, b1ba,
                                     g1A, bn1A, hA, outA,
                                     nullptr, nullptr, nullptr, nullptr, NA);
}

// round 7
// speedup vs baseline: 1.4240x; 1.0375x over previous
#include <cuda_runtime.h>
#include <cuda_bf16.h>
#include <mma.h>
#include <math.h>

using namespace nvcuda;

// ---------------------------------------------------------------------------
// HeteroGAT encoder.
//   - 6 GEMMs via bf16 split-3 WMMA; persistent CTAs keep the FULL split
//     weight matrix resident in smem (loaded/converted once per CTA);
//     full-K X tile staged per row tile -> 2 syncs per 128-row tile.
//   - CSR-by-dst; fused aggregate + softmax + LN + relu + residual
//     (+ next-layer scores fused into layer-0 epilogue)
// ---------------------------------------------------------------------------

#define NMAX 50176
#define EMAX 500000

__device__ float g_hA[NMAX * 128];
__device__ float g_hB[NMAX * 128];
__device__ float g_t1[NMAX * 128];
__device__ float g_t2[NMAX * 128];
__device__ float g_as1_0[NMAX * 4], g_ad1_0[NMAX * 4];
__device__ float g_as2_0[NMAX * 4], g_ad2_0[NMAX * 4];
__device__ float g_as1_1[NMAX], g_ad1_1[NMAX];
__device__ float g_as2_1[NMAX], g_ad2_1[NMAX];
__device__ float g_wp[8][128 * 4];
__device__ int g_rpAB[NMAX + 1], g_rpBA[NMAX + 1];
__device__ int g_cur[NMAX], g_deg[NMAX];
__device__ int g_srcAB[EMAX], g_srcBA[EMAX];

__device__ __forceinline__ float warpSum(float v) {
#pragma unroll
    for (int o = 16; o > 0; o >>= 1) v += __shfl_xor_sync(0xffffffffu, v, o);
    return v;
}
__device__ __forceinline__ float warpMax(float v) {
#pragma unroll
    for (int o = 16; o > 0; o >>= 1) v = fmaxf(v, __shfl_xor_sync(0xffffffffu, v, o));
    return v;
}

// ---------------------------------------------------------------------------
// bf16 split-3 WMMA GEMM, persistent CTAs, W resident in smem.
// out[M,128] = X[M,K] @ W[K,128] (+ bias). out NMAX-padded.
// dynamic smem: Whi[K][136] Wlo[K][136] Xhi[128][K+8] Xlo[128][K+8]  (bf16)
// ---------------------------------------------------------------------------
template <int K>
__global__ __launch_bounds__(256) void gemm_wres(
    const float* __restrict__ X, const float* __restrict__ W,
    const float* __restrict__ bias, float* __restrict__ out, int M) {
    constexpr int WLD = 136;      // W row stride (cols=128)
    constexpr int XLD = K + 8;    // X row stride (cols=K)
    constexpr int SPR = K / 4;    // float4 slots per X row

    extern __shared__ __nv_bfloat16 smx[];
    __nv_bfloat16* Whi = smx;                       // K*WLD
    __nv_bfloat16* Wlo = Whi + K * WLD;             // K*WLD
    __nv_bfloat16* Xhi = Wlo + K * WLD;             // 128*XLD
    __nv_bfloat16* Xlo = Xhi + 128 * XLD;           // 128*XLD
    __shared__ float Bs[16][WLD];

    const int tid = threadIdx.x;
    const int wid = tid >> 5;
    const int warp_row = (wid >> 1) * 32;
    const int warp_col = (wid & 1) * 64;

    // ---- one-time: bias tile + full W split ----
    if (bias) {
#pragma unroll
        for (int i = tid; i < 16 * 128; i += 256) Bs[i >> 7][i & 127] = bias[i & 127];
    }
    for (int idx = tid; idx < K * 32; idx += 256) {   // K*128/4 float4 slots
        int r = idx >> 5;
        int c4 = (idx & 31) * 4;
        float4 v = *(const float4*)&W[(size_t)r * 128 + c4];
        float vv[4] = {v.x, v.y, v.z, v.w};
        __nv_bfloat16 h[4], l[4];
#pragma unroll
        for (int q = 0; q < 4; q++) {
            h[q] = __float2bfloat16(vv[q]);
            l[q] = __float2bfloat16(vv[q] - __bfloat162float(h[q]));
        }
        *(__nv_bfloat162*)&Whi[r * WLD + c4] = __nv_bfloat162{h[0], h[1]};
        *(__nv_bfloat162*)&Whi[r * WLD + c4 + 2] = __nv_bfloat162{h[2], h[3]};
        *(__nv_bfloat162*)&Wlo[r * WLD + c4] = __nv_bfloat162{l[0], l[1]};
        *(__nv_bfloat162*)&Wlo[r * WLD + c4 + 2] = __nv_bfloat162{l[2], l[3]};
    }
    __syncthreads();

    const int nTiles = (M + 127) >> 7;
    for (int t = blockIdx.x; t < nTiles; t += gridDim.x) {
        const int block_row = t * 128;

        // ---- stage full-K X tile (128 x K), split hi/lo ----
#pragma unroll
        for (int p = 0; p < 128 * SPR / 256; p++) {
            int idx = tid + p * 256;
            int r = idx / SPR;
            int c4 = (idx % SPR) * 4;
            int gr = block_row + r;
            float4 v = make_float4(0.f, 0.f, 0.f, 0.f);
            if (gr < M) v = *(const float4*)&X[(size_t)gr * K + c4];
            float vv[4] = {v.x, v.y, v.z, v.w};
            __nv_bfloat16 h[4], l[4];
#pragma unroll
            for (int q = 0; q < 4; q++) {
                h[q] = __float2bfloat16(vv[q]);
                l[q] = __float2bfloat16(vv[q] - __bfloat162float(h[q]));
            }
            *(__nv_bfloat162*)&Xhi[r * XLD + c4] = __nv_bfloat162{h[0], h[1]};
            *(__nv_bfloat162*)&Xhi[r * XLD + c4 + 2] = __nv_bfloat162{h[2], h[3]};
            *(__nv_bfloat162*)&Xlo[r * XLD + c4] = __nv_bfloat162{l[0], l[1]};
            *(__nv_bfloat162*)&Xlo[r * XLD + c4 + 2] = __nv_bfloat162{l[2], l[3]};
        }
        __syncthreads();

        wmma::fragment<wmma::accumulator, 16, 16, 16, float> acc[2][4];
#pragma unroll
        for (int i = 0; i < 2; i++)
#pragma unroll
            for (int j = 0; j < 4; j++) {
                if (bias)
                    wmma::load_matrix_sync(acc[i][j], &Bs[0][warp_col + j * 16], WLD,
                                           wmma::mem_row_major);
                else
                    wmma::fill_fragment(acc[i][j], 0.f);
            }

#pragma unroll 2
        for (int ks = 0; ks < K; ks += 16) {
            wmma::fragment<wmma::matrix_a, 16, 16, 16, __nv_bfloat16, wmma::row_major> ahi[2], alo[2];
            wmma::fragment<wmma::matrix_b, 16, 16, 16, __nv_bfloat16, wmma::row_major> bhi[4], blo[4];
#pragma unroll
            for (int i = 0; i < 2; i++) {
                wmma::load_matrix_sync(ahi[i], &Xhi[(warp_row + i * 16) * XLD + ks], XLD);
                wmma::load_matrix_sync(alo[i], &Xlo[(warp_row + i * 16) * XLD + ks], XLD);
            }
#pragma unroll
            for (int j = 0; j < 4; j++) {
                wmma::load_matrix_sync(bhi[j], &Whi[ks * WLD + warp_col + j * 16], WLD);
                wmma::load_matrix_sync(blo[j], &Wlo[ks * WLD + warp_col + j * 16], WLD);
            }
#pragma unroll
            for (int i = 0; i < 2; i++)
#pragma unroll
                for (int j = 0; j < 4; j++) {
                    wmma::mma_sync(acc[i][j], ahi[i], blo[j], acc[i][j]);
                    wmma::mma_sync(acc[i][j], alo[i], bhi[j], acc[i][j]);
                    wmma::mma_sync(acc[i][j], ahi[i], bhi[j], acc[i][j]);
                }
        }

#pragma unroll
        for (int i = 0; i < 2; i++)
#pragma unroll
            for (int j = 0; j < 4; j++) {
                size_t off = (size_t)(block_row + warp_row + i * 16) * 128 + warp_col + j * 16;
                wmma::store_matrix_sync(&out[off], acc[i][j], 128, wmma::mem_row_major);
            }
        __syncthreads();
    }
}

template <int K>
constexpr int gemm_smem_bytes() {
    return (2 * K * 136 + 2 * 128 * (K + 8)) * (int)sizeof(__nv_bfloat16);
}

// ---------------------------------------------------------------------------
// all 4 attention-weight projections, one launch
// ---------------------------------------------------------------------------
__global__ void make_wp_all(
    const float* __restrict__ w0ab, const float* __restrict__ as0ab, const float* __restrict__ ad0ab,
    const float* __restrict__ w0ba, const float* __restrict__ as0ba, const float* __restrict__ ad0ba,
    const float* __restrict__ w1ab, const float* __restrict__ as1ab, const float* __restrict__ ad1ab,
    const float* __restrict__ w1ba, const float* __restrict__ as1ba, const float* __restrict__ ad1ba) {
    __shared__ float Ws[64][129];
    int cfg = blockIdx.x;
    const float* W = cfg == 0 ? w0ab : cfg == 1 ? w0ba : cfg == 2 ? w1ab : w1ba;
    const float* avs = cfg == 0 ? as0ab : cfg == 1 ? as0ba : cfg == 2 ? as1ab : as1ba;
    const float* avd = cfg == 0 ? ad0ab : cfg == 1 ? ad0ba : cfg == 2 ? ad1ab : ad1ba;
    const int H = (cfg < 2) ? 4 : 1;
    const int D = 128 / H;
    float* wpS = g_wp[cfg * 2];
    float* wpD = g_wp[cfg * 2 + 1];

    int tid = threadIdx.x;
    float ss[4] = {0.f, 0.f, 0.f, 0.f}, sd[4] = {0.f, 0.f, 0.f, 0.f};
    for (int chunk = 0; chunk < 2; chunk++) {
        int r0 = chunk * 64;
        for (int i = tid; i < 64 * 128; i += 256)
            Ws[i >> 7][i & 127] = W[(size_t)(r0 + (i >> 7)) * 128 + (i & 127)];
        __syncthreads();
        int k = tid;
        if (k < 128 && k >= r0 && k < r0 + 64) {
            for (int h = 0; h < H; h++) {
                float a = 0.f, b = 0.f;
                for (int d = 0; d < D; d++) {
                    float w = Ws[k - r0][h * D + d];
                    a += w * avs[h * D + d];
                    b += w * avd[h * D + d];
                }
                ss[h] = a; sd[h] = b;
            }
        }
        __syncthreads();
    }
    if (tid < 128)
        for (int h = 0; h < H; h++) { wpS[tid * H + h] = ss[h]; wpD[tid * H + h] = sd[h]; }
}

// ---------------------------------------------------------------------------
template <int H>
__global__ void node_scores2(const float* __restrict__ X, const float* __restrict__ wpS,
                             const float* __restrict__ wpD, float* __restrict__ outS,
                             float* __restrict__ outD, int N) {
    int w = (blockIdx.x * blockDim.x + threadIdx.x) >> 5;
    int lane = threadIdx.x & 31;
    if (w >= N) return;
    const float* xr = X + (size_t)w * 128;
    float accS[H], accD[H];
#pragma unroll
    for (int h = 0; h < H; h++) { accS[h] = 0.f; accD[h] = 0.f; }
#pragma unroll
    for (int kk = 0; kk < 4; kk++) {
        int k = lane + kk * 32;
        float x = xr[k];
#pragma unroll
        for (int h = 0; h < H; h++) {
            accS[h] += x * wpS[k * H + h];
            accD[h] += x * wpD[k * H + h];
        }
    }
#pragma unroll
    for (int h = 0; h < H; h++) { accS[h] = warpSum(accS[h]); accD[h] = warpSum(accD[h]); }
    if (lane == 0) {
#pragma unroll
        for (int h = 0; h < H; h++) { outS[w * H + h] = accS[h]; outD[w * H + h] = accD[h]; }
    }
}

// ---------------------------------------------------------------------------
// CSR build
// ---------------------------------------------------------------------------
__global__ void edge_hist(const int* __restrict__ dst, int* __restrict__ deg, int E) {
    int e = blockIdx.x * blockDim.x + threadIdx.x;
    if (e < E) atomicAdd(&deg[dst[e]], 1);
}
__global__ void edge_fill(const int* __restrict__ src, const int* __restrict__ dst,
                          int* __restrict__ cursor, int* __restrict__ col, int E) {
    int e = blockIdx.x * blockDim.x + threadIdx.x;
    if (e < E) {
        int p = atomicAdd(&cursor[dst[e]], 1);
        col[p] = src[e];
    }
}
__global__ __launch_bounds__(1024) void exscan_block(
    const int* __restrict__ deg, int* __restrict__ rowptr, int* __restrict__ cursor, int N) {
    __shared__ int sums[1024];
    int t = threadIdx.x;
    int chunk = (N + 1023) / 1024;
    int b0 = t * chunk;
    int b1 = min(b0 + chunk, N);
    int s = 0;
    for (int i = b0; i < b1; i++) s += deg[i];
    sums[t] = s;
    __syncthreads();
    for (int off = 1; off < 1024; off <<= 1) {
        int v = (t >= off) ? sums[t - off] : 0;
        __syncthreads();
        sums[t] += v;
        __syncthreads();
    }
    int run = (t == 0) ? 0 : sums[t - 1];
    for (int i = b0; i < b1; i++) {
        rowptr[i] = run;
        cursor[i] = run;
        run += deg[i];
    }
    if (t == 1023) rowptr[N] = run;
}

// ---------------------------------------------------------------------------
// fused GAT aggregate + softmax + bias + LN + relu + residual (+ next scores)
// warp per destination node; CAP=64 smem fast path (deg>64 fallback kept)
// ---------------------------------------------------------------------------
template <int H, bool SC>
__global__ __launch_bounds__(256) void gat_fused(
    const int* __restrict__ rowptr, const int* __restrict__ srcs,
    const float* __restrict__ a_s, const float* __restrict__ a_d,
    const float* __restrict__ tS, const float* __restrict__ gbias,
    const float* __restrict__ gamma, const float* __restrict__ beta,
    const float* __restrict__ hprev, float* __restrict__ hout,
    const float* __restrict__ wpSn, const float* __restrict__ wpDn,
    float* __restrict__ outSn, float* __restrict__ outDn, int Ndst) {
    const int D = 128 / H;
    const int CAP = 64;
    __shared__ float s_ex[8][CAP * H];
    __shared__ int s_src[8][CAP];

    int wid = (blockIdx.x * blockDim.x + threadIdx.x) >> 5;
    int w = threadIdx.x >> 5;
    int lane = threadIdx.x & 31;
    if (wid >= Ndst) return;
    int start = rowptr[wid];
    int end = rowptr[wid + 1];
    int deg = end - start;

    float adh[H];
#pragma unroll
    for (int h = 0; h < H; h++) adh[h] = a_d[wid * H + h];

    const int hh = (lane * 4) / D;
    float4 acc = make_float4(0.f, 0.f, 0.f, 0.f);

    if (deg <= CAP) {
        float sc[2][H];
        int nIt = (deg + 31) >> 5;
        float mx[H];
#pragma unroll
        for (int h = 0; h < H; h++) mx[h] = -3.0e38f;
#pragma unroll
        for (int i = 0; i < 2; i++) {
            int j = lane + i * 32;
            if (i < nIt && j < deg) {
                int s = srcs[start + j];
                s_src[w][j] = s;
#pragma unroll
                for (int h = 0; h < H; h++) {
                    float v = a_s[s * H + h] + adh[h];
                    v = v > 0.f ? v : 0.2f * v;
                    sc[i][h] = v;
                    mx[h] = fmaxf(mx[h], v);
                }
            }
        }
#pragma unroll
        for (int h = 0; h < H; h++) mx[h] = warpMax(mx[h]);

        float sm[H];
#pragma unroll
        for (int h = 0; h < H; h++) sm[h] = 0.f;
#pragma unroll
        for (int i = 0; i < 2; i++) {
            int j = lane + i * 32;
            if (i < nIt && j < deg) {
#pragma unroll
                for (int h = 0; h < H; h++) {
                    float ex = __expf(sc[i][h] - mx[h]);
                    sm[h] += ex;
                    s_ex[w][j * H + h] = ex;
                }
            }
        }
#pragma unroll
        for (int h = 0; h < H; h++) sm[h] = warpSum(sm[h]);
        float invh;
        if (H == 1) invh = 1.f / (sm[0] + 1e-16f);
        else invh = 1.f / ((hh == 0 ? sm[0] : hh == 1 ? sm[1] : hh == 2 ? sm[2] : sm[3]) + 1e-16f);

        __syncwarp();
        int e = 0;
        for (; e + 4 <= deg; e += 4) {
            float ex0 = s_ex[w][(e + 0) * H + hh];
            float ex1 = s_ex[w][(e + 1) * H + hh];
            float ex2 = s_ex[w][(e + 2) * H + hh];
            float ex3 = s_ex[w][(e + 3) * H + hh];
            int s0 = s_src[w][e + 0], s1 = s_src[w][e + 1];
            int s2 = s_src[w][e + 2], s3 = s_src[w][e + 3];
            float4 v0 = *(const float4*)(tS + (size_t)s0 * 128 + lane * 4);
            float4 v1 = *(const float4*)(tS + (size_t)s1 * 128 + lane * 4);
            float4 v2 = *(const float4*)(tS + (size_t)s2 * 128 + lane * 4);
            float4 v3 = *(const float4*)(tS + (size_t)s3 * 128 + lane * 4);
            acc.x += v0.x * ex0 + v1.x * ex1 + v2.x * ex2 + v3.x * ex3;
            acc.y += v0.y * ex0 + v1.y * ex1 + v2.y * ex2 + v3.y * ex3;
            acc.z += v0.z * ex0 + v1.z * ex1 + v2.z * ex2 + v3.z * ex3;
            acc.w += v0.w * ex0 + v1.w * ex1 + v2.w * ex2 + v3.w * ex3;
        }
        for (; e < deg; e++) {
            float ex = s_ex[w][e * H + hh];
            int s = s_src[w][e];
            float4 v = *(const float4*)(tS + (size_t)s * 128 + lane * 4);
            acc.x += v.x * ex; acc.y += v.y * ex; acc.z += v.z * ex; acc.w += v.w * ex;
        }
        acc.x *= invh; acc.y *= invh; acc.z *= invh; acc.w *= invh;
    } else {
        float mx[H];
#pragma unroll
        for (int h = 0; h < H; h++) mx[h] = -3.0e38f;
        for (int e = start + lane; e < end; e += 32) {
            int s = srcs[e];
#pragma unroll
            for (int h = 0; h < H; h++) {
                float v = a_s[s * H + h] + adh[h];
                v = v > 0.f ? v : 0.2f * v;
                mx[h] = fmaxf(mx[h], v);
            }
        }
#pragma unroll
        for (int h = 0; h < H; h++) mx[h] = warpMax(mx[h]);
        float sm[H];
#pragma unroll
        for (int h = 0; h < H; h++) sm[h] = 0.f;
        for (int e = start + lane; e < end; e += 32) {
            int s = srcs[e];
#pragma unroll
            for (int h = 0; h < H; h++) {
                float v = a_s[s * H + h] + adh[h];
                v = v > 0.f ? v : 0.2f * v;
                sm[h] += __expf(v - mx[h]);
            }
        }
#pragma unroll
        for (int h = 0; h < H; h++) sm[h] = warpSum(sm[h]);
        float invh;
        if (H == 1) invh = 1.f / (sm[0] + 1e-16f);
        else invh = 1.f / ((hh == 0 ? sm[0] : hh == 1 ? sm[1] : hh == 2 ? sm[2] : sm[3]) + 1e-16f);
        float mxh = (H == 1) ? mx[0] : (hh == 0 ? mx[0] : hh == 1 ? mx[1] : hh == 2 ? mx[2] : mx[3]);
        float adhh = (H == 1) ? adh[0] : (hh == 0 ? adh[0] : hh == 1 ? adh[1] : hh == 2 ? adh[2] : adh[3]);
        for (int e = start; e < end; e++) {
            int s = srcs[e];
            float v = a_s[s * H + hh] + adhh;
            v = v > 0.f ? v : 0.2f * v;
            float ex = __expf(v - mxh);
            float4 t = *(const float4*)(tS + (size_t)s * 128 + lane * 4);
            acc.x += t.x * ex; acc.y += t.y * ex; acc.z += t.z * ex; acc.w += t.w * ex;
        }
        acc.x *= invh; acc.y *= invh; acc.z *= invh; acc.w *= invh;
    }

    size_t rbase = (size_t)wid * 128 + lane * 4;
    float4 bb = *(const float4*)(gbias + lane * 4);
    acc.x += bb.x; acc.y += bb.y; acc.z += bb.z; acc.w += bb.w;
    float mu = warpSum(acc.x + acc.y + acc.z + acc.w) * (1.f / 128.f);
    float dx = acc.x - mu, dy = acc.y - mu, dz = acc.z - mu, dw = acc.w - mu;
    float var = warpSum(dx * dx + dy * dy + dz * dz + dw * dw) * (1.f / 128.f);
    float r = rsqrtf(var + 1e-5f);
    float4 gg = *(const float4*)(gamma + lane * 4);
    float4 be = *(const float4*)(beta + lane * 4);
    float4 hp = *(const float4*)(hprev + rbase);
    float4 o;
    o.x = fmaxf(0.f, dx * r * gg.x + be.x) + hp.x;
    o.y = fmaxf(0.f, dy * r * gg.y + be.y) + hp.y;
    o.z = fmaxf(0.f, dz * r * gg.z + be.z) + hp.z;
    o.w = fmaxf(0.f, dw * r * gg.w + be.w) + hp.w;
    *(float4*)(hout + rbase) = o;

    if (SC) {
        float4 ws = *(const float4*)(wpSn + lane * 4);
        float4 wd = *(const float4*)(wpDn + lane * 4);
        float sS = o.x * ws.x + o.y * ws.y + o.z * ws.z + o.w * ws.w;
        float sD = o.x * wd.x + o.y * wd.y + o.z * wd.z + o.w * wd.w;
        sS = warpSum(sS);
        sD = warpSum(sD);
        if (lane == 0) { outSn[wid] = sS; outDn[wid] = sD; }
    }
}

// ---------------------------------------------------------------------------
static inline void* sym(const void* s) {
    void* p = nullptr;
    cudaGetSymbolAddress(&p, s);
    return p;
}

extern "C" void kernel_launch(void* const* d_in, const int* in_sizes, int n_in,
                              void* d_out, int out_size) {
    const float* x_A = (const float*)d_in[0];
    const float* x_B = (const float*)d_in[1];
    const float* pWA = (const float*)d_in[2];
    const float* pbA = (const float*)d_in[3];
    const float* pWB = (const float*)d_in[4];
    const float* pbB = (const float*)d_in[5];
    const float* w0ab = (const float*)d_in[6];
    const float* as0ab = (const float*)d_in[7];
    const float* ad0ab = (const float*)d_in[8];
    const float* b0ab = (const float*)d_in[9];
    const float* w0ba = (const float*)d_in[10];
    const float* as0ba = (const float*)d_in[11];
    const float* ad0ba = (const float*)d_in[12];
    const float* b0ba = (const float*)d_in[13];
    const float* w1ab = (const float*)d_in[14];
    const float* as1ab = (const float*)d_in[15];
    const float* ad1ab = (const float*)d_in[16];
    const float* b1ab = (const float*)d_in[17];
    const float* w1ba = (const float*)d_in[18];
    const float* as1ba = (const float*)d_in[19];
    const float* ad1ba = (const float*)d_in[20];
    const float* b1ba = (const float*)d_in[21];
    const float* g0A = (const float*)d_in[22];
    const float* bn0A = (const float*)d_in[23];
    const float* g0B = (const float*)d_in[24];
    const float* bn0B = (const float*)d_in[25];
    const float* g1A = (const float*)d_in[26];
    const float* bn1A = (const float*)d_in[27];
    const float* g1B = (const float*)d_in[28];
    const float* bn1B = (const float*)d_in[29];
    const int* ei_AB = (const int*)d_in[30];
    const int* ei_BA = (const int*)d_in[31];

    const int NA = in_sizes[0] / 128;
    const int NB = in_sizes[1] / 64;
    const int E = in_sizes[30] / 2;

    float* hA = (float*)sym(g_hA);
    float* hB = (float*)sym(g_hB);
    float* t1 = (float*)sym(g_t1);
    float* t2 = (float*)sym(g_t2);
    float* as1_0 = (float*)sym(g_as1_0);
    float* ad1_0 = (float*)sym(g_ad1_0);
    float* as2_0 = (float*)sym(g_as2_0);
    float* ad2_0 = (float*)sym(g_ad2_0);
    float* as1_1 = (float*)sym(g_as1_1);
    float* ad1_1 = (float*)sym(g_ad1_1);
    float* as2_1 = (float*)sym(g_as2_1);
    float* ad2_1 = (float*)sym(g_ad2_1);
    float* wp = (float*)sym(g_wp);
    int* rpAB = (int*)sym(g_rpAB);
    int* rpBA = (int*)sym(g_rpBA);
    int* cur = (int*)sym(g_cur);
    int* deg = (int*)sym(g_deg);
    int* srcAB = (int*)sym(g_srcAB);
    int* srcBA = (int*)sym(g_srcBA);

    float* wpS1_0 = wp + 0 * 512, *wpD1_0 = wp + 1 * 512;
    float* wpS2_0 = wp + 2 * 512, *wpD2_0 = wp + 3 * 512;
    float* wpS1_1 = wp + 4 * 512, *wpD1_1 = wp + 5 * 512;
    float* wpS2_1 = wp + 6 * 512, *wpD2_1 = wp + 7 * 512;

    const int TB = 256;
    const int eb = (E + TB - 1) / TB;
    const int wbA = (NA * 32 + TB - 1) / TB;
    const int wbB = (NB * 32 + TB - 1) / TB;
    const int PG = 148;

    constexpr int SM128 = gemm_smem_bytes<128>();
    constexpr int SM64 = gemm_smem_bytes<64>();
    cudaFuncSetAttribute(gemm_wres<128>, cudaFuncAttributeMaxDynamicSharedMemorySize, SM128);
    cudaFuncSetAttribute(gemm_wres<64>, cudaFuncAttributeMaxDynamicSharedMemorySize, SM64);

    // launches 1-5, then big GEMM at slot 6 for ncu
    cudaMemsetAsync(deg, 0, NB * sizeof(int));
    edge_hist<<<eb, TB>>>(ei_AB + E, deg, E);
    exscan_block<<<1, 1024>>>(deg, rpAB, cur, NB);
    edge_fill<<<eb, TB>>>(ei_AB, ei_AB + E, cur, srcAB, E);
    cudaMemsetAsync(deg, 0, NA * sizeof(int));

    gemm_wres<128><<<PG, TB, SM128>>>(x_A, pWA, pbA, hA, NA);   // launch #6

    edge_hist<<<eb, TB>>>(ei_BA + E, deg, E);
    exscan_block<<<1, 1024>>>(deg, rpBA, cur, NA);
    edge_fill<<<eb, TB>>>(ei_BA, ei_BA + E, cur, srcBA, E);

    gemm_wres<64><<<PG, TB, SM64>>>(x_B, pWB, pbB, hB, NB);
    make_wp_all<<<4, 256>>>(w0ab, as0ab, ad0ab, w0ba, as0ba, ad0ba,
                            w1ab, as1ab, ad1ab, w1ba, as1ba, ad1ba);

    // ================= layer 0 (H=4) =================
    gemm_wres<128><<<PG, TB, SM128>>>(hA, w0ab, nullptr, t1, NA);
    gemm_wres<128><<<PG, TB, SM128>>>(hB, w0ba, nullptr, t2, NB);

    node_scores2<4><<<wbA, TB>>>(hA, wpS1_0, wpD2_0, as1_0, ad2_0, NA);
    node_scores2<4><<<wbB, TB>>>(hB, wpS2_0, wpD1_0, as2_0, ad1_0, NB);

    gat_fused<4, true><<<wbB, TB>>>(rpAB, srcAB, as1_0, ad1_0, t1, b0ab,
                                    g0B, bn0B, hB, hB,
                                    wpS2_1, wpD1_1, as2_1, ad1_1, NB);
    gat_fused<4, true><<<wbA, TB>>>(rpBA, srcBA, as2_0, ad2_0, t2, b0ba,
                                    g0A, bn0A, hA, hA,
                                    wpS1_1, wpD2_1, as1_1, ad2_1, NA);

    // ================= layer 1 (H=1) =================
    gemm_wres<128><<<PG, TB, SM128>>>(hA, w1ab, nullptr, t1, NA);
    gemm_wres<128><<<PG, TB, SM128>>>(hB, w1ba, nullptr, t2, NB);

    float* outA = (float*)d_out;
    float* outB = outA + (size_t)NA * 128;
    gat_fused<1, false><<<wbB, TB>>>(rpAB, srcAB, as1_1, ad1_1, t1, b1ab,
                                     g1B, bn1B, hB, outB,
                                     nullptr, nullptr, nullptr, nullptr, NB);
    gat_fused<1, false><<<wbA, TB>>>(rpBA, srcBA, as2_1, ad2_1, t2, b1ba,
                                     g1A, bn1A, hA, outA,
                                     nullptr, nullptr, nullptr, nullptr, NA);
}

// round 8
// speedup vs baseline: 2.0117x; 1.4127x over previous
#include <cuda_runtime.h>
#include <cuda_bf16.h>
#include <mma.h>
#include <math.h>

using namespace nvcuda;

// ---------------------------------------------------------------------------
// HeteroGAT encoder.
//   - 6 GEMMs via bf16 split-3 WMMA, W resident in smem (round-7 kernel)
//   - CSR-by-dst; fused aggregate + softmax + LN + relu + residual
//   - NEW: multi-stream graph parallelism — A-pipeline / B-pipeline / CSR+wp
//     forked off the capture stream with events; t3/t4 kill layer-1 WAR syncs
// ---------------------------------------------------------------------------

#define NMAX 50176
#define EMAX 500000

__device__ float g_hA[NMAX * 128];
__device__ float g_hB[NMAX * 128];
__device__ float g_t1[NMAX * 128];
__device__ float g_t2[NMAX * 128];
__device__ float g_t3[NMAX * 128];
__device__ float g_t4[NMAX * 128];
__device__ float g_as1_0[NMAX * 4], g_ad1_0[NMAX * 4];
__device__ float g_as2_0[NMAX * 4], g_ad2_0[NMAX * 4];
__device__ float g_as1_1[NMAX], g_ad1_1[NMAX];
__device__ float g_as2_1[NMAX], g_ad2_1[NMAX];
__device__ float g_wp[8][128 * 4];
__device__ int g_rpAB[NMAX + 1], g_rpBA[NMAX + 1];
__device__ int g_cur[NMAX], g_deg[NMAX];
__device__ int g_srcAB[EMAX], g_srcBA[EMAX];

__device__ __forceinline__ float warpSum(float v) {
#pragma unroll
    for (int o = 16; o > 0; o >>= 1) v += __shfl_xor_sync(0xffffffffu, v, o);
    return v;
}
__device__ __forceinline__ float warpMax(float v) {
#pragma unroll
    for (int o = 16; o > 0; o >>= 1) v = fmaxf(v, __shfl_xor_sync(0xffffffffu, v, o));
    return v;
}

// ---------------------------------------------------------------------------
// bf16 split-3 WMMA GEMM, persistent CTAs, W resident in smem.
// ---------------------------------------------------------------------------
template <int K>
__global__ __launch_bounds__(256) void gemm_wres(
    const float* __restrict__ X, const float* __restrict__ W,
    const float* __restrict__ bias, float* __restrict__ out, int M) {
    constexpr int WLD = 136;
    constexpr int XLD = K + 8;
    constexpr int SPR = K / 4;

    extern __shared__ __nv_bfloat16 smx[];
    __nv_bfloat16* Whi = smx;
    __nv_bfloat16* Wlo = Whi + K * WLD;
    __nv_bfloat16* Xhi = Wlo + K * WLD;
    __nv_bfloat16* Xlo = Xhi + 128 * XLD;
    __shared__ float Bs[16][WLD];

    const int tid = threadIdx.x;
    const int wid = tid >> 5;
    const int warp_row = (wid >> 1) * 32;
    const int warp_col = (wid & 1) * 64;

    if (bias) {
#pragma unroll
        for (int i = tid; i < 16 * 128; i += 256) Bs[i >> 7][i & 127] = bias[i & 127];
    }
    for (int idx = tid; idx < K * 32; idx += 256) {
        int r = idx >> 5;
        int c4 = (idx & 31) * 4;
        float4 v = *(const float4*)&W[(size_t)r * 128 + c4];
        float vv[4] = {v.x, v.y, v.z, v.w};
        __nv_bfloat16 h[4], l[4];
#pragma unroll
        for (int q = 0; q < 4; q++) {
            h[q] = __float2bfloat16(vv[q]);
            l[q] = __float2bfloat16(vv[q] - __bfloat162float(h[q]));
        }
        *(__nv_bfloat162*)&Whi[r * WLD + c4] = __nv_bfloat162{h[0], h[1]};
        *(__nv_bfloat162*)&Whi[r * WLD + c4 + 2] = __nv_bfloat162{h[2], h[3]};
        *(__nv_bfloat162*)&Wlo[r * WLD + c4] = __nv_bfloat162{l[0], l[1]};
        *(__nv_bfloat162*)&Wlo[r * WLD + c4 + 2] = __nv_bfloat162{l[2], l[3]};
    }
    __syncthreads();

    const int nTiles = (M + 127) >> 7;
    for (int t = blockIdx.x; t < nTiles; t += gridDim.x) {
        const int block_row = t * 128;
#pragma unroll
        for (int p = 0; p < 128 * SPR / 256; p++) {
            int idx = tid + p * 256;
            int r = idx / SPR;
            int c4 = (idx % SPR) * 4;
            int gr = block_row + r;
            float4 v = make_float4(0.f, 0.f, 0.f, 0.f);
            if (gr < M) v = *(const float4*)&X[(size_t)gr * K + c4];
            float vv[4] = {v.x, v.y, v.z, v.w};
            __nv_bfloat16 h[4], l[4];
#pragma unroll
            for (int q = 0; q < 4; q++) {
                h[q] = __float2bfloat16(vv[q]);
                l[q] = __float2bfloat16(vv[q] - __bfloat162float(h[q]));
            }
            *(__nv_bfloat162*)&Xhi[r * XLD + c4] = __nv_bfloat162{h[0], h[1]};
            *(__nv_bfloat162*)&Xhi[r * XLD + c4 + 2] = __nv_bfloat162{h[2], h[3]};
            *(__nv_bfloat162*)&Xlo[r * XLD + c4] = __nv_bfloat162{l[0], l[1]};
            *(__nv_bfloat162*)&Xlo[r * XLD + c4 + 2] = __nv_bfloat162{l[2], l[3]};
        }
        __syncthreads();

        wmma::fragment<wmma::accumulator, 16, 16, 16, float> acc[2][4];
#pragma unroll
        for (int i = 0; i < 2; i++)
#pragma unroll
            for (int j = 0; j < 4; j++) {
                if (bias)
                    wmma::load_matrix_sync(acc[i][j], &Bs[0][warp_col + j * 16], WLD,
                                           wmma::mem_row_major);
                else
                    wmma::fill_fragment(acc[i][j], 0.f);
            }

#pragma unroll 2
        for (int ks = 0; ks < K; ks += 16) {
            wmma::fragment<wmma::matrix_a, 16, 16, 16, __nv_bfloat16, wmma::row_major> ahi[2], alo[2];
            wmma::fragment<wmma::matrix_b, 16, 16, 16, __nv_bfloat16, wmma::row_major> bhi[4], blo[4];
#pragma unroll
            for (int i = 0; i < 2; i++) {
                wmma::load_matrix_sync(ahi[i], &Xhi[(warp_row + i * 16) * XLD + ks], XLD);
                wmma::load_matrix_sync(alo[i], &Xlo[(warp_row + i * 16) * XLD + ks], XLD);
            }
#pragma unroll
            for (int j = 0; j < 4; j++) {
                wmma::load_matrix_sync(bhi[j], &Whi[ks * WLD + warp_col + j * 16], WLD);
                wmma::load_matrix_sync(blo[j], &Wlo[ks * WLD + warp_col + j * 16], WLD);
            }
#pragma unroll
            for (int i = 0; i < 2; i++)
#pragma unroll
                for (int j = 0; j < 4; j++) {
                    wmma::mma_sync(acc[i][j], ahi[i], blo[j], acc[i][j]);
                    wmma::mma_sync(acc[i][j], alo[i], bhi[j], acc[i][j]);
                    wmma::mma_sync(acc[i][j], ahi[i], bhi[j], acc[i][j]);
                }
        }

#pragma unroll
        for (int i = 0; i < 2; i++)
#pragma unroll
            for (int j = 0; j < 4; j++) {
                size_t off = (size_t)(block_row + warp_row + i * 16) * 128 + warp_col + j * 16;
                wmma::store_matrix_sync(&out[off], acc[i][j], 128, wmma::mem_row_major);
            }
        __syncthreads();
    }
}

template <int K>
constexpr int gemm_smem_bytes() {
    return (2 * K * 136 + 2 * 128 * (K + 8)) * (int)sizeof(__nv_bfloat16);
}

// ---------------------------------------------------------------------------
__global__ void make_wp_all(
    const float* __restrict__ w0ab, const float* __restrict__ as0ab, const float* __restrict__ ad0ab,
    const float* __restrict__ w0ba, const float* __restrict__ as0ba, const float* __restrict__ ad0ba,
    const float* __restrict__ w1ab, const float* __restrict__ as1ab, const float* __restrict__ ad1ab,
    const float* __restrict__ w1ba, const float* __restrict__ as1ba, const float* __restrict__ ad1ba) {
    __shared__ float Ws[64][129];
    int cfg = blockIdx.x;
    const float* W = cfg == 0 ? w0ab : cfg == 1 ? w0ba : cfg == 2 ? w1ab : w1ba;
    const float* avs = cfg == 0 ? as0ab : cfg == 1 ? as0ba : cfg == 2 ? as1ab : as1ba;
    const float* avd = cfg == 0 ? ad0ab : cfg == 1 ? ad0ba : cfg == 2 ? ad1ab : ad1ba;
    const int H = (cfg < 2) ? 4 : 1;
    const int D = 128 / H;
    float* wpS = g_wp[cfg * 2];
    float* wpD = g_wp[cfg * 2 + 1];

    int tid = threadIdx.x;
    float ss[4] = {0.f, 0.f, 0.f, 0.f}, sd[4] = {0.f, 0.f, 0.f, 0.f};
    for (int chunk = 0; chunk < 2; chunk++) {
        int r0 = chunk * 64;
        for (int i = tid; i < 64 * 128; i += 256)
            Ws[i >> 7][i & 127] = W[(size_t)(r0 + (i >> 7)) * 128 + (i & 127)];
        __syncthreads();
        int k = tid;
        if (k < 128 && k >= r0 && k < r0 + 64) {
            for (int h = 0; h < H; h++) {
                float a = 0.f, b = 0.f;
                for (int d = 0; d < D; d++) {
                    float w = Ws[k - r0][h * D + d];
                    a += w * avs[h * D + d];
                    b += w * avd[h * D + d];
                }
                ss[h] = a; sd[h] = b;
            }
        }
        __syncthreads();
    }
    if (tid < 128)
        for (int h = 0; h < H; h++) { wpS[tid * H + h] = ss[h]; wpD[tid * H + h] = sd[h]; }
}

// ---------------------------------------------------------------------------
template <int H>
__global__ void node_scores2(const float* __restrict__ X, const float* __restrict__ wpS,
                             const float* __restrict__ wpD, float* __restrict__ outS,
                             float* __restrict__ outD, int N) {
    int w = (blockIdx.x * blockDim.x + threadIdx.x) >> 5;
    int lane = threadIdx.x & 31;
    if (w >= N) return;
    const float* xr = X + (size_t)w * 128;
    float accS[H], accD[H];
#pragma unroll
    for (int h = 0; h < H; h++) { accS[h] = 0.f; accD[h] = 0.f; }
#pragma unroll
    for (int kk = 0; kk < 4; kk++) {
        int k = lane + kk * 32;
        float x = xr[k];
#pragma unroll
        for (int h = 0; h < H; h++) {
            accS[h] += x * wpS[k * H + h];
            accD[h] += x * wpD[k * H + h];
        }
    }
#pragma unroll
    for (int h = 0; h < H; h++) { accS[h] = warpSum(accS[h]); accD[h] = warpSum(accD[h]); }
    if (lane == 0) {
#pragma unroll
        for (int h = 0; h < H; h++) { outS[w * H + h] = accS[h]; outD[w * H + h] = accD[h]; }
    }
}

// ---------------------------------------------------------------------------
__global__ void edge_hist(const int* __restrict__ dst, int* __restrict__ deg, int E) {
    int e = blockIdx.x * blockDim.x + threadIdx.x;
    if (e < E) atomicAdd(&deg[dst[e]], 1);
}
__global__ void edge_fill(const int* __restrict__ src, const int* __restrict__ dst,
                          int* __restrict__ cursor, int* __restrict__ col, int E) {
    int e = blockIdx.x * blockDim.x + threadIdx.x;
    if (e < E) {
        int p = atomicAdd(&cursor[dst[e]], 1);
        col[p] = src[e];
    }
}
__global__ __launch_bounds__(1024) void exscan_block(
    const int* __restrict__ deg, int* __restrict__ rowptr, int* __restrict__ cursor, int N) {
    __shared__ int sums[1024];
    int t = threadIdx.x;
    int chunk = (N + 1023) / 1024;
    int b0 = t * chunk;
    int b1 = min(b0 + chunk, N);
    int s = 0;
    for (int i = b0; i < b1; i++) s += deg[i];
    sums[t] = s;
    __syncthreads();
    for (int off = 1; off < 1024; off <<= 1) {
        int v = (t >= off) ? sums[t - off] : 0;
        __syncthreads();
        sums[t] += v;
        __syncthreads();
    }
    int run = (t == 0) ? 0 : sums[t - 1];
    for (int i = b0; i < b1; i++) {
        rowptr[i] = run;
        cursor[i] = run;
        run += deg[i];
    }
    if (t == 1023) rowptr[N] = run;
}
__global__ void zero_int(int* __restrict__ p, int n) {
    int i = blockIdx.x * blockDim.x + threadIdx.x;
    if (i < n) p[i] = 0;
}

// ---------------------------------------------------------------------------
// fused GAT aggregate + softmax + bias + LN + relu + residual (+ next scores)
// ---------------------------------------------------------------------------
template <int H, bool SC>
__global__ __launch_bounds__(256) void gat_fused(
    const int* __restrict__ rowptr, const int* __restrict__ srcs,
    const float* __restrict__ a_s, const float* __restrict__ a_d,
    const float* __restrict__ tS, const float* __restrict__ gbias,
    const float* __restrict__ gamma, const float* __restrict__ beta,
    const float* __restrict__ hprev, float* __restrict__ hout,
    const float* __restrict__ wpSn, const float* __restrict__ wpDn,
    float* __restrict__ outSn, float* __restrict__ outDn, int Ndst) {
    const int D = 128 / H;
    const int CAP = 64;
    __shared__ float s_ex[8][CAP * H];
    __shared__ int s_src[8][CAP];

    int wid = (blockIdx.x * blockDim.x + threadIdx.x) >> 5;
    int w = threadIdx.x >> 5;
    int lane = threadIdx.x & 31;
    if (wid >= Ndst) return;
    int start = rowptr[wid];
    int end = rowptr[wid + 1];
    int deg = end - start;

    float adh[H];
#pragma unroll
    for (int h = 0; h < H; h++) adh[h] = a_d[wid * H + h];

    const int hh = (lane * 4) / D;
    float4 acc = make_float4(0.f, 0.f, 0.f, 0.f);

    if (deg <= CAP) {
        float sc[2][H];
        int nIt = (deg + 31) >> 5;
        float mx[H];
#pragma unroll
        for (int h = 0; h < H; h++) mx[h] = -3.0e38f;
#pragma unroll
        for (int i = 0; i < 2; i++) {
            int j = lane + i * 32;
            if (i < nIt && j < deg) {
                int s = srcs[start + j];
                s_src[w][j] = s;
#pragma unroll
                for (int h = 0; h < H; h++) {
                    float v = a_s[s * H + h] + adh[h];
                    v = v > 0.f ? v : 0.2f * v;
                    sc[i][h] = v;
                    mx[h] = fmaxf(mx[h], v);
                }
            }
        }
#pragma unroll
        for (int h = 0; h < H; h++) mx[h] = warpMax(mx[h]);

        float sm[H];
#pragma unroll
        for (int h = 0; h < H; h++) sm[h] = 0.f;
#pragma unroll
        for (int i = 0; i < 2; i++) {
            int j = lane + i * 32;
            if (i < nIt && j < deg) {
#pragma unroll
                for (int h = 0; h < H; h++) {
                    float ex = __expf(sc[i][h] - mx[h]);
                    sm[h] += ex;
                    s_ex[w][j * H + h] = ex;
                }
            }
        }
#pragma unroll
        for (int h = 0; h < H; h++) sm[h] = warpSum(sm[h]);
        float invh;
        if (H == 1) invh = 1.f / (sm[0] + 1e-16f);
        else invh = 1.f / ((hh == 0 ? sm[0] : hh == 1 ? sm[1] : hh == 2 ? sm[2] : sm[3]) + 1e-16f);

        __syncwarp();
        int e = 0;
        for (; e + 4 <= deg; e += 4) {
            float ex0 = s_ex[w][(e + 0) * H + hh];
            float ex1 = s_ex[w][(e + 1) * H + hh];
            float ex2 = s_ex[w][(e + 2) * H + hh];
            float ex3 = s_ex[w][(e + 3) * H + hh];
            int s0 = s_src[w][e + 0], s1 = s_src[w][e + 1];
            int s2 = s_src[w][e + 2], s3 = s_src[w][e + 3];
            float4 v0 = *(const float4*)(tS + (size_t)s0 * 128 + lane * 4);
            float4 v1 = *(const float4*)(tS + (size_t)s1 * 128 + lane * 4);
            float4 v2 = *(const float4*)(tS + (size_t)s2 * 128 + lane * 4);
            float4 v3 = *(const float4*)(tS + (size_t)s3 * 128 + lane * 4);
            acc.x += v0.x * ex0 + v1.x * ex1 + v2.x * ex2 + v3.x * ex3;
            acc.y += v0.y * ex0 + v1.y * ex1 + v2.y * ex2 + v3.y * ex3;
            acc.z += v0.z * ex0 + v1.z * ex1 + v2.z * ex2 + v3.z * ex3;
            acc.w += v0.w * ex0 + v1.w * ex1 + v2.w * ex2 + v3.w * ex3;
        }
        for (; e < deg; e++) {
            float ex = s_ex[w][e * H + hh];
            int s = s_src[w][e];
            float4 v = *(const float4*)(tS + (size_t)s * 128 + lane * 4);
            acc.x += v.x * ex; acc.y += v.y * ex; acc.z += v.z * ex; acc.w += v.w * ex;
        }
        acc.x *= invh; acc.y *= invh; acc.z *= invh; acc.w *= invh;
    } else {
        float mx[H];
#pragma unroll
        for (int h = 0; h < H; h++) mx[h] = -3.0e38f;
        for (int e = start + lane; e < end; e += 32) {
            int s = srcs[e];
#pragma unroll
            for (int h = 0; h < H; h++) {
                float v = a_s[s * H + h] + adh[h];
                v = v > 0.f ? v : 0.2f * v;
                mx[h] = fmaxf(mx[h], v);
            }
        }
#pragma unroll
        for (int h = 0; h < H; h++) mx[h] = warpMax(mx[h]);
        float sm[H];
#pragma unroll
        for (int h = 0; h < H; h++) sm[h] = 0.f;
        for (int e = start + lane; e < end; e += 32) {
            int s = srcs[e];
#pragma unroll
            for (int h = 0; h < H; h++) {
                float v = a_s[s * H + h] + adh[h];
                v = v > 0.f ? v : 0.2f * v;
                sm[h] += __expf(v - mx[h]);
            }
        }
#pragma unroll
        for (int h = 0; h < H; h++) sm[h] = warpSum(sm[h]);
        float invh;
        if (H == 1) invh = 1.f / (sm[0] + 1e-16f);
        else invh = 1.f / ((hh == 0 ? sm[0] : hh == 1 ? sm[1] : hh == 2 ? sm[2] : sm[3]) + 1e-16f);
        float mxh = (H == 1) ? mx[0] : (hh == 0 ? mx[0] : hh == 1 ? mx[1] : hh == 2 ? mx[2] : mx[3]);
        float adhh = (H == 1) ? adh[0] : (hh == 0 ? adh[0] : hh == 1 ? adh[1] : hh == 2 ? adh[2] : adh[3]);
        for (int e = start; e < end; e++) {
            int s = srcs[e];
            float v = a_s[s * H + hh] + adhh;
            v = v > 0.f ? v : 0.2f * v;
            float ex = __expf(v - mxh);
            float4 t = *(const float4*)(tS + (size_t)s * 128 + lane * 4);
            acc.x += t.x * ex; acc.y += t.y * ex; acc.z += t.z * ex; acc.w += t.w * ex;
        }
        acc.x *= invh; acc.y *= invh; acc.z *= invh; acc.w *= invh;
    }

    size_t rbase = (size_t)wid * 128 + lane * 4;
    float4 bb = *(const float4*)(gbias + lane * 4);
    acc.x += bb.x; acc.y += bb.y; acc.z += bb.z; acc.w += bb.w;
    float mu = warpSum(acc.x + acc.y + acc.z + acc.w) * (1.f / 128.f);
    float dx = acc.x - mu, dy = acc.y - mu, dz = acc.z - mu, dw = acc.w - mu;
    float var = warpSum(dx * dx + dy * dy + dz * dz + dw * dw) * (1.f / 128.f);
    float r = rsqrtf(var + 1e-5f);
    float4 gg = *(const float4*)(gamma + lane * 4);
    float4 be = *(const float4*)(beta + lane * 4);
    float4 hp = *(const float4*)(hprev + rbase);
    float4 o;
    o.x = fmaxf(0.f, dx * r * gg.x + be.x) + hp.x;
    o.y = fmaxf(0.f, dy * r * gg.y + be.y) + hp.y;
    o.z = fmaxf(0.f, dz * r * gg.z + be.z) + hp.z;
    o.w = fmaxf(0.f, dw * r * gg.w + be.w) + hp.w;
    *(float4*)(hout + rbase) = o;

    if (SC) {
        float4 ws = *(const float4*)(wpSn + lane * 4);
        float4 wd = *(const float4*)(wpDn + lane * 4);
        float sS = o.x * ws.x + o.y * ws.y + o.z * ws.z + o.w * ws.w;
        float sD = o.x * wd.x + o.y * wd.y + o.z * wd.z + o.w * wd.w;
        sS = warpSum(sS);
        sD = warpSum(sD);
        if (lane == 0) { outSn[wid] = sS; outDn[wid] = sD; }
    }
}

// ---------------------------------------------------------------------------
static inline void* sym(const void* s) {
    void* p = nullptr;
    cudaGetSymbolAddress(&p, s);
    return p;
}

extern "C" void kernel_launch(void* const* d_in, const int* in_sizes, int n_in,
                              void* d_out, int out_size) {
    const float* x_A = (const float*)d_in[0];
    const float* x_B = (const float*)d_in[1];
    const float* pWA = (const float*)d_in[2];
    const float* pbA = (const float*)d_in[3];
    const float* pWB = (const float*)d_in[4];
    const float* pbB = (const float*)d_in[5];
    const float* w0ab = (const float*)d_in[6];
    const float* as0ab = (const float*)d_in[7];
    const float* ad0ab = (const float*)d_in[8];
    const float* b0ab = (const float*)d_in[9];
    const float* w0ba = (const float*)d_in[10];
    const float* as0ba = (const float*)d_in[11];
    const float* ad0ba = (const float*)d_in[12];
    const float* b0ba = (const float*)d_in[13];
    const float* w1ab = (const float*)d_in[14];
    const float* as1ab = (const float*)d_in[15];
    const float* ad1ab = (const float*)d_in[16];
    const float* b1ab = (const float*)d_in[17];
    const float* w1ba = (const float*)d_in[18];
    const float* as1ba = (const float*)d_in[19];
    const float* ad1ba = (const float*)d_in[20];
    const float* b1ba = (const float*)d_in[21];
    const float* g0A = (const float*)d_in[22];
    const float* bn0A = (const float*)d_in[23];
    const float* g0B = (const float*)d_in[24];
    const float* bn0B = (const float*)d_in[25];
    const float* g1A = (const float*)d_in[26];
    const float* bn1A = (const float*)d_in[27];
    const float* g1B = (const float*)d_in[28];
    const float* bn1B = (const float*)d_in[29];
    const int* ei_AB = (const int*)d_in[30];
    const int* ei_BA = (const int*)d_in[31];

    const int NA = in_sizes[0] / 128;
    const int NB = in_sizes[1] / 64;
    const int E = in_sizes[30] / 2;

    float* hA = (float*)sym(g_hA);
    float* hB = (float*)sym(g_hB);
    float* t1 = (float*)sym(g_t1);
    float* t2 = (float*)sym(g_t2);
    float* t3 = (float*)sym(g_t3);
    float* t4 = (float*)sym(g_t4);
    float* as1_0 = (float*)sym(g_as1_0);
    float* ad1_0 = (float*)sym(g_ad1_0);
    float* as2_0 = (float*)sym(g_as2_0);
    float* ad2_0 = (float*)sym(g_ad2_0);
    float* as1_1 = (float*)sym(g_as1_1);
    float* ad1_1 = (float*)sym(g_ad1_1);
    float* as2_1 = (float*)sym(g_as2_1);
    float* ad2_1 = (float*)sym(g_ad2_1);
    float* wp = (float*)sym(g_wp);
    int* rpAB = (int*)sym(g_rpAB);
    int* rpBA = (int*)sym(g_rpBA);
    int* cur = (int*)sym(g_cur);
    int* deg = (int*)sym(g_deg);
    int* srcAB = (int*)sym(g_srcAB);
    int* srcBA = (int*)sym(g_srcBA);

    float* wpS1_0 = wp + 0 * 512, *wpD1_0 = wp + 1 * 512;
    float* wpS2_0 = wp + 2 * 512, *wpD2_0 = wp + 3 * 512;
    float* wpS1_1 = wp + 4 * 512, *wpD1_1 = wp + 5 * 512;
    float* wpS2_1 = wp + 6 * 512, *wpD2_1 = wp + 7 * 512;

    const int TB = 256;
    const int eb = (E + TB - 1) / TB;
    const int wbA = (NA * 32 + TB - 1) / TB;
    const int wbB = (NB * 32 + TB - 1) / TB;
    const int zbA = (NA + 255) / 256, zbB = (NB + 255) / 256;
    const int PG = 148;

    constexpr int SM128 = gemm_smem_bytes<128>();
    constexpr int SM64 = gemm_smem_bytes<64>();

    // --- lazy one-time setup (first call = correctness run, NOT captured) ---
    static bool s_init = false;
    static cudaStream_t s1, s2, s3;
    static cudaEvent_t eRoot, eWP, eCsrAB, eCsrBA, eSA, eSB, eA0AB, eA0BA, eF1, eF2;
    if (!s_init) {
        cudaStreamCreateWithFlags(&s1, cudaStreamNonBlocking);
        cudaStreamCreateWithFlags(&s2, cudaStreamNonBlocking);
        cudaStreamCreateWithFlags(&s3, cudaStreamNonBlocking);
        cudaEventCreateWithFlags(&eRoot, cudaEventDisableTiming);
        cudaEventCreateWithFlags(&eWP, cudaEventDisableTiming);
        cudaEventCreateWithFlags(&eCsrAB, cudaEventDisableTiming);
        cudaEventCreateWithFlags(&eCsrBA, cudaEventDisableTiming);
        cudaEventCreateWithFlags(&eSA, cudaEventDisableTiming);
        cudaEventCreateWithFlags(&eSB, cudaEventDisableTiming);
        cudaEventCreateWithFlags(&eA0AB, cudaEventDisableTiming);
        cudaEventCreateWithFlags(&eA0BA, cudaEventDisableTiming);
        cudaEventCreateWithFlags(&eF1, cudaEventDisableTiming);
        cudaEventCreateWithFlags(&eF2, cudaEventDisableTiming);
        cudaFuncSetAttribute(gemm_wres<128>, cudaFuncAttributeMaxDynamicSharedMemorySize, SM128);
        cudaFuncSetAttribute(gemm_wres<64>, cudaFuncAttributeMaxDynamicSharedMemorySize, SM64);
        s_init = true;
    }

    float* outA = (float*)d_out;
    float* outB = outA + (size_t)NA * 128;

    // ---- fork ----
    cudaEventRecord(eRoot, 0);
    cudaStreamWaitEvent(s1, eRoot, 0);
    cudaStreamWaitEvent(s2, eRoot, 0);
    cudaStreamWaitEvent(s3, eRoot, 0);

    // s3: wp projections, then both CSR chains
    make_wp_all<<<4, 256, 0, s3>>>(w0ab, as0ab, ad0ab, w0ba, as0ba, ad0ba,
                                   w1ab, as1ab, ad1ab, w1ba, as1ba, ad1ba);
    cudaEventRecord(eWP, s3);

    // s1/s2: projection + layer-0 GEMMs
    gemm_wres<128><<<PG, TB, SM128, s1>>>(x_A, pWA, pbA, hA, NA);
    gemm_wres<128><<<PG, TB, SM128, s1>>>(hA, w0ab, nullptr, t1, NA);
    gemm_wres<64><<<PG, TB, SM64, s2>>>(x_B, pWB, pbB, hB, NB);
    gemm_wres<128><<<PG, TB, SM128, s2>>>(hB, w0ba, nullptr, t2, NB);

    // s3: CSR AB then BA
    zero_int<<<zbB, 256, 0, s3>>>(deg, NB);
    edge_hist<<<eb, TB, 0, s3>>>(ei_AB + E, deg, E);
    exscan_block<<<1, 1024, 0, s3>>>(deg, rpAB, cur, NB);
    edge_fill<<<eb, TB, 0, s3>>>(ei_AB, ei_AB + E, cur, srcAB, E);
    cudaEventRecord(eCsrAB, s3);
    zero_int<<<zbA, 256, 0, s3>>>(deg, NA);
    edge_hist<<<eb, TB, 0, s3>>>(ei_BA + E, deg, E);
    exscan_block<<<1, 1024, 0, s3>>>(deg, rpBA, cur, NA);
    edge_fill<<<eb, TB, 0, s3>>>(ei_BA, ei_BA + E, cur, srcBA, E);
    cudaEventRecord(eCsrBA, s3);

    // layer-0 scores
    cudaStreamWaitEvent(s1, eWP, 0);
    node_scores2<4><<<wbA, TB, 0, s1>>>(hA, wpS1_0, wpD2_0, as1_0, ad2_0, NA);
    cudaEventRecord(eSA, s1);
    cudaStreamWaitEvent(s2, eWP, 0);
    node_scores2<4><<<wbB, TB, 0, s2>>>(hB, wpS2_0, wpD1_0, as2_0, ad1_0, NB);
    cudaEventRecord(eSB, s2);

    // layer-0 aggregates (concurrent)
    cudaStreamWaitEvent(s1, eSB, 0);
    cudaStreamWaitEvent(s1, eCsrAB, 0);
    gat_fused<4, true><<<wbB, TB, 0, s1>>>(rpAB, srcAB, as1_0, ad1_0, t1, b0ab,
                                           g0B, bn0B, hB, hB,
                                           wpS2_1, wpD1_1, as2_1, ad1_1, NB);
    cudaEventRecord(eA0AB, s1);
    cudaStreamWaitEvent(s2, eSA, 0);
    cudaStreamWaitEvent(s2, eCsrBA, 0);
    gat_fused<4, true><<<wbA, TB, 0, s2>>>(rpBA, srcBA, as2_0, ad2_0, t2, b0ba,
                                           g0A, bn0A, hA, hA,
                                           wpS1_1, wpD2_1, as1_1, ad2_1, NA);
    cudaEventRecord(eA0BA, s2);

    // layer-1 GEMMs (fresh buffers t3/t4 -> no WAR against layer-0 aggs)
    gemm_wres<128><<<PG, TB, SM128, s1>>>(hB, w1ba, nullptr, t4, NB);  // after A0AB (s1)
    gemm_wres<128><<<PG, TB, SM128, s2>>>(hA, w1ab, nullptr, t3, NA);  // after A0BA (s2)

    // layer-1 aggregates (concurrent)
    cudaStreamWaitEvent(s1, eA0BA, 0);
    gat_fused<1, false><<<wbA, TB, 0, s1>>>(rpBA, srcBA, as2_1, ad2_1, t4, b1ba,
                                            g1A, bn1A, hA, outA,
                                            nullptr, nullptr, nullptr, nullptr, NA);
    cudaEventRecord(eF1, s1);
    cudaStreamWaitEvent(s2, eA0AB, 0);
    gat_fused<1, false><<<wbB, TB, 0, s2>>>(rpAB, srcAB, as1_1, ad1_1, t3, b1ab,
                                            g1B, bn1B, hB, outB,
                                            nullptr, nullptr, nullptr, nullptr, NB);
    cudaEventRecord(eF2, s2);

    // ---- join back to capture stream ----
    cudaStreamWaitEvent(0, eF1, 0);
    cudaStreamWaitEvent(0, eF2, 0);
}